// round 1
// baseline (speedup 1.0000x reference)
#include <cuda_runtime.h>
#include <math.h>

// Problem constants: x [16, 512, 64, 64] fp32; C=512, GROUPS=32, n=h*w=4096.
typedef unsigned long long u64;

#define BATCH 16
#define CCH   512
#define NPIX  4096

// Scratch buffers (allocation-free rule: __device__ globals).
__device__ float g_hn  [(size_t)BATCH * CCH * NPIX];
__device__ float g_q   [(size_t)BATCH * CCH * NPIX];
__device__ float g_k   [(size_t)BATCH * CCH * NPIX];
__device__ float g_v   [(size_t)BATCH * CCH * NPIX];
__device__ float g_o   [(size_t)BATCH * CCH * NPIX];
__device__ float g_attn[(size_t)BATCH * CCH * CCH];

// ---------------- packed f32x2 helpers (sm_103a FFMA2 pipe) ----------------
__device__ __forceinline__ u64 dupf(float x) {
    u64 r;
    asm("mov.b64 %0, {%1, %1};" : "=l"(r) : "f"(x));
    return r;
}
__device__ __forceinline__ u64 ffma2(u64 a, u64 b, u64 c) {
    u64 d;
    asm("fma.rn.f32x2 %0, %1, %2, %3;" : "=l"(d) : "l"(a), "l"(b), "l"(c));
    return d;
}
__device__ __forceinline__ float2 unpk(u64 v) {
    float2 f;
    asm("mov.b64 {%0, %1}, %2;" : "=f"(f.x), "=f"(f.y) : "l"(v));
    return f;
}

// ---------------- GroupNorm: one block per (batch, group) ----------------
__global__ void groupnorm_kernel(const float* __restrict__ x,
                                 const float* __restrict__ gamma,
                                 const float* __restrict__ beta,
                                 float* __restrict__ hn)
{
    const int GELEMS = 16 * NPIX;  // 16 channels per group * 4096 pixels = 65536
    int b = blockIdx.x >> 5;
    int g = blockIdx.x & 31;
    size_t base = (size_t)b * (CCH * NPIX) + (size_t)g * GELEMS;
    const float4* xp = (const float4*)(x + base);
    float4* hp = (float4*)(hn + base);
    int tid = threadIdx.x;  // 256 threads

    float s = 0.f, ss = 0.f;
    for (int i = tid; i < GELEMS / 4; i += 256) {
        float4 vv = xp[i];
        s  += vv.x + vv.y + vv.z + vv.w;
        ss += vv.x * vv.x + vv.y * vv.y + vv.z * vv.z + vv.w * vv.w;
    }
    __shared__ float rs[256], rq[256];
    rs[tid] = s; rq[tid] = ss;
    __syncthreads();
    for (int o = 128; o > 0; o >>= 1) {
        if (tid < o) { rs[tid] += rs[tid + o]; rq[tid] += rq[tid + o]; }
        __syncthreads();
    }
    float mean = rs[0] * (1.f / GELEMS);
    float var  = rq[0] * (1.f / GELEMS) - mean * mean;   // ddof=0, matches jnp.var
    float rstd = rsqrtf(var + 1e-6f);

    for (int i = tid; i < GELEMS / 4; i += 256) {
        int ch = (g << 4) + (i >> 10);  // 1024 float4 per channel
        float ga = gamma[ch] * rstd;
        float be = beta[ch] - mean * ga;
        float4 vv = xp[i];
        vv.x = vv.x * ga + be; vv.y = vv.y * ga + be;
        vv.z = vv.z * ga + be; vv.w = vv.w * ga + be;
        hp[i] = vv;
    }
}

// ---------------- GEMM NN: C[z] = A[z] (MxK) * B[z] (KxN) + bias + resid ----------------
// 128x128 tile, BK=8, 256 threads, 8x8 micro-tile (4+4 split), f32x2 inner product.
#define BM 128
#define BN 128
#define BK 8

__global__ void __launch_bounds__(256) gemm_nn_kernel(
    const float* __restrict__ A, long long sA,
    const float* __restrict__ B, long long sB,
    float* __restrict__ C, long long sC,
    const float* __restrict__ bias,
    const float* __restrict__ resid,   // batch stride sC; nullable
    int M, int N, int K)
{
    __shared__ __align__(16) float As[BK][BM];
    __shared__ __align__(16) float Bs[BK][BN];

    int z = blockIdx.z;
    const float* Ab = A + (size_t)z * sA;
    const float* Bb = B + (size_t)z * sB;
    float* Cb = C + (size_t)z * sC;

    int tid = threadIdx.x;
    int row0 = blockIdx.y * BM;
    int col0 = blockIdx.x * BN;

    // global load mapping
    int arow = tid >> 1;           // 0..127
    int acol = (tid & 1) * 4;      // 0 or 4
    int brow = tid >> 5;           // 0..7
    int bcol = (tid & 31) * 4;     // 0..124

    // compute mapping: rows {ta..ta+3, ta+64..ta+67}, cols {tc..tc+3, tc+64..tc+67}
    int ta = (tid >> 4) * 4;
    int tc = (tid & 15) * 4;

    u64 acc[8][4];
#pragma unroll
    for (int i = 0; i < 8; i++)
#pragma unroll
        for (int j = 0; j < 4; j++) acc[i][j] = 0ull;

    const float* Aptr = Ab + (size_t)(row0 + arow) * K + acol;
    const float* Bptr = Bb + (size_t)brow * N + col0 + bcol;

    for (int k0 = 0; k0 < K; k0 += BK) {
        float4 av = *(const float4*)Aptr;  Aptr += BK;
        float4 bv = *(const float4*)Bptr;  Bptr += (size_t)BK * N;
        As[acol + 0][arow] = av.x; As[acol + 1][arow] = av.y;
        As[acol + 2][arow] = av.z; As[acol + 3][arow] = av.w;
        *(float4*)(&Bs[brow][bcol]) = bv;
        __syncthreads();
#pragma unroll
        for (int kk = 0; kk < BK; kk++) {
            float4 a0 = *(const float4*)(&As[kk][ta]);
            float4 a1 = *(const float4*)(&As[kk][ta + 64]);
            ulonglong2 bA = *(const ulonglong2*)(&Bs[kk][tc]);
            ulonglong2 bB = *(const ulonglong2*)(&Bs[kk][tc + 64]);
            u64 bp[4] = { bA.x, bA.y, bB.x, bB.y };
            float am[8] = { a0.x, a0.y, a0.z, a0.w, a1.x, a1.y, a1.z, a1.w };
#pragma unroll
            for (int i = 0; i < 8; i++) {
                u64 ad = dupf(am[i]);
#pragma unroll
                for (int j = 0; j < 4; j++)
                    acc[i][j] = ffma2(bp[j], ad, acc[i][j]);
            }
        }
        __syncthreads();
    }

#pragma unroll
    for (int i = 0; i < 8; i++) {
        int r = row0 + ta + ((i < 4) ? i : (60 + i));   // i>=4 -> ta+64+(i-4)
        float bv_ = bias ? bias[r] : 0.f;
        float2 c0 = unpk(acc[i][0]), c1 = unpk(acc[i][1]);
        float2 c2 = unpk(acc[i][2]), c3 = unpk(acc[i][3]);
        float4 o0 = make_float4(c0.x + bv_, c0.y + bv_, c1.x + bv_, c1.y + bv_);
        float4 o1 = make_float4(c2.x + bv_, c2.y + bv_, c3.x + bv_, c3.y + bv_);
        size_t off = (size_t)r * N + col0 + tc;
        if (resid) {
            const float* Rb = resid + (size_t)z * sC;
            float4 r0 = *(const float4*)(Rb + off);
            float4 r1 = *(const float4*)(Rb + off + 64);
            o0.x += r0.x; o0.y += r0.y; o0.z += r0.z; o0.w += r0.w;
            o1.x += r1.x; o1.y += r1.y; o1.z += r1.z; o1.w += r1.w;
        }
        *(float4*)(Cb + off) = o0;
        *(float4*)(Cb + off + 64) = o1;
    }
}

// ---------------- GEMM NT: C[z] = scale * A[z] (MxK) * B[z]^T (B is NxK) ----------------
__global__ void __launch_bounds__(256) gemm_nt_kernel(
    const float* __restrict__ A, long long sA,
    const float* __restrict__ B, long long sB,
    float* __restrict__ C, long long sC,
    int M, int N, int K, float scale)
{
    __shared__ __align__(16) float As[BK][BM];
    __shared__ __align__(16) float Bs[BK][BN];

    int z = blockIdx.z;
    const float* Ab = A + (size_t)z * sA;
    const float* Bb = B + (size_t)z * sB;
    float* Cb = C + (size_t)z * sC;

    int tid = threadIdx.x;
    int row0 = blockIdx.y * BM;
    int col0 = blockIdx.x * BN;

    int arow = tid >> 1;
    int acol = (tid & 1) * 4;

    int ta = (tid >> 4) * 4;
    int tc = (tid & 15) * 4;

    u64 acc[8][4];
#pragma unroll
    for (int i = 0; i < 8; i++)
#pragma unroll
        for (int j = 0; j < 4; j++) acc[i][j] = 0ull;

    const float* Aptr = Ab + (size_t)(row0 + arow) * K + acol;
    const float* Bptr = Bb + (size_t)(col0 + arow) * K + acol;

    for (int k0 = 0; k0 < K; k0 += BK) {
        float4 av = *(const float4*)Aptr;  Aptr += BK;
        float4 bv = *(const float4*)Bptr;  Bptr += BK;
        As[acol + 0][arow] = av.x; As[acol + 1][arow] = av.y;
        As[acol + 2][arow] = av.z; As[acol + 3][arow] = av.w;
        Bs[acol + 0][arow] = bv.x; Bs[acol + 1][arow] = bv.y;
        Bs[acol + 2][arow] = bv.z; Bs[acol + 3][arow] = bv.w;
        __syncthreads();
#pragma unroll
        for (int kk = 0; kk < BK; kk++) {
            float4 a0 = *(const float4*)(&As[kk][ta]);
            float4 a1 = *(const float4*)(&As[kk][ta + 64]);
            ulonglong2 bA = *(const ulonglong2*)(&Bs[kk][tc]);
            ulonglong2 bB = *(const ulonglong2*)(&Bs[kk][tc + 64]);
            u64 bp[4] = { bA.x, bA.y, bB.x, bB.y };
            float am[8] = { a0.x, a0.y, a0.z, a0.w, a1.x, a1.y, a1.z, a1.w };
#pragma unroll
            for (int i = 0; i < 8; i++) {
                u64 ad = dupf(am[i]);
#pragma unroll
                for (int j = 0; j < 4; j++)
                    acc[i][j] = ffma2(bp[j], ad, acc[i][j]);
            }
        }
        __syncthreads();
    }

#pragma unroll
    for (int i = 0; i < 8; i++) {
        int r = row0 + ta + ((i < 4) ? i : (60 + i));
        float2 c0 = unpk(acc[i][0]), c1 = unpk(acc[i][1]);
        float2 c2 = unpk(acc[i][2]), c3 = unpk(acc[i][3]);
        float4 o0 = make_float4(c0.x * scale, c0.y * scale, c1.x * scale, c1.y * scale);
        float4 o1 = make_float4(c2.x * scale, c2.y * scale, c3.x * scale, c3.y * scale);
        size_t off = (size_t)r * N + col0 + tc;
        *(float4*)(Cb + off) = o0;
        *(float4*)(Cb + off + 64) = o1;
    }
}

// ---------------- Softmax over last dim (rows of 512), one warp per row ----------------
__global__ void softmax_kernel(float* __restrict__ attn)
{
    int gw = (blockIdx.x * blockDim.x + threadIdx.x) >> 5;
    int lane = threadIdx.x & 31;
    if (gw >= BATCH * CCH) return;
    float* row = attn + (size_t)gw * CCH;
    float v[16];
    float m = -3.4e38f;
#pragma unroll
    for (int i = 0; i < 16; i++) { v[i] = row[lane + (i << 5)]; m = fmaxf(m, v[i]); }
#pragma unroll
    for (int o = 16; o > 0; o >>= 1) m = fmaxf(m, __shfl_xor_sync(0xffffffffu, m, o));
    float s = 0.f;
#pragma unroll
    for (int i = 0; i < 16; i++) { v[i] = __expf(v[i] - m); s += v[i]; }
#pragma unroll
    for (int o = 16; o > 0; o >>= 1) s += __shfl_xor_sync(0xffffffffu, s, o);
    float inv = 1.f / s;
#pragma unroll
    for (int i = 0; i < 16; i++) row[lane + (i << 5)] = v[i] * inv;
}

// ---------------- launch ----------------
extern "C" void kernel_launch(void* const* d_in, const int* in_sizes, int n_in,
                              void* d_out, int out_size)
{
    const float* x     = (const float*)d_in[0];
    const float* gamma = (const float*)d_in[1];
    const float* beta  = (const float*)d_in[2];
    const float* Wq    = (const float*)d_in[3];
    const float* bq    = (const float*)d_in[4];
    const float* Wk    = (const float*)d_in[5];
    const float* bk    = (const float*)d_in[6];
    const float* Wv    = (const float*)d_in[7];
    const float* bv    = (const float*)d_in[8];
    const float* Wo    = (const float*)d_in[9];
    const float* bo    = (const float*)d_in[10];
    float* out = (float*)d_out;

    float *hn, *q, *k, *v, *o, *attn;
    cudaGetSymbolAddress((void**)&hn,   g_hn);
    cudaGetSymbolAddress((void**)&q,    g_q);
    cudaGetSymbolAddress((void**)&k,    g_k);
    cudaGetSymbolAddress((void**)&v,    g_v);
    cudaGetSymbolAddress((void**)&o,    g_o);
    cudaGetSymbolAddress((void**)&attn, g_attn);

    const long long sF = (long long)CCH * NPIX;   // per-batch feature-map stride
    const long long sAt = (long long)CCH * CCH;   // per-batch attention stride
    const float scale = 1.0f / sqrtf((float)CCH);

    // 1) GroupNorm
    groupnorm_kernel<<<BATCH * 32, 256>>>(x, gamma, beta, hn);

    // 2) Q/K/V 1x1 convs: [512x512] * [512x4096] per batch
    dim3 gFeat(NPIX / BN, CCH / BM, BATCH);
    gemm_nn_kernel<<<gFeat, 256>>>(Wq, 0, hn, sF, q, sF, bq, nullptr, CCH, NPIX, CCH);
    gemm_nn_kernel<<<gFeat, 256>>>(Wk, 0, hn, sF, k, sF, bk, nullptr, CCH, NPIX, CCH);
    gemm_nn_kernel<<<gFeat, 256>>>(Wv, 0, hn, sF, v, sF, bv, nullptr, CCH, NPIX, CCH);

    // 3) scores = q @ k^T * c^-0.5 : [512x4096] * [4096x512]
    dim3 gAttn(CCH / BN, CCH / BM, BATCH);
    gemm_nt_kernel<<<gAttn, 256>>>(q, sF, k, sF, attn, sAt, CCH, CCH, NPIX, scale);

    // 4) softmax over rows of 512
    softmax_kernel<<<(BATCH * CCH * 32) / 256, 256>>>(attn);

    // 5) out = attn @ v : [512x512] * [512x4096] (batched A)
    gemm_nn_kernel<<<gFeat, 256>>>(attn, sAt, v, sF, o, sF, nullptr, nullptr, CCH, NPIX, CCH);

    // 6) final = Wo @ out + bo + x
    gemm_nn_kernel<<<gFeat, 256>>>(Wo, 0, o, sF, out, sF, bo, x, CCH, NPIX, CCH);
}

// round 3
// speedup vs baseline: 2.6838x; 2.6838x over previous
#include <cuda_runtime.h>
#include <math.h>
#include <stdint.h>

#define BATCH 16
#define CCH   512
#define NPIX  4096

// ---------------- scratch (__device__ globals; no allocation allowed) ----------------
__device__ float g_hnT [(size_t)BATCH * NPIX * CCH];   // [b, pixel, channel]
__device__ float g_q   [(size_t)BATCH * CCH * NPIX];   // [b, channel, pixel]
__device__ float g_k   [(size_t)BATCH * CCH * NPIX];
__device__ float g_vT  [(size_t)BATCH * NPIX * CCH];   // [b, pixel, channel]
__device__ float g_oT  [(size_t)BATCH * NPIX * CCH];
__device__ float g_attn[(size_t)BATCH * CCH * CCH];
__device__ float2 g_stats[BATCH * 32];                 // mean, rstd per (b, group)

__device__ __forceinline__ float tf32r(float x) {   // round-to-nearest tf32
    float y; asm("cvt.rna.tf32.f32 %0, %1;" : "=f"(y) : "f"(x)); return y;
}

__device__ __forceinline__ void mma_tf32_16x8x8(float* d, const uint32_t* a, const uint32_t* b) {
    asm volatile(
        "mma.sync.aligned.m16n8k8.row.col.f32.tf32.tf32.f32 "
        "{%0,%1,%2,%3}, {%4,%5,%6,%7}, {%8,%9}, {%0,%1,%2,%3};"
        : "+f"(d[0]), "+f"(d[1]), "+f"(d[2]), "+f"(d[3])
        : "r"(a[0]), "r"(a[1]), "r"(a[2]), "r"(a[3]), "r"(b[0]), "r"(b[1]));
}

// ---------------- GroupNorm stats: one block per (batch, group) ----------------
__global__ void gn_stats_kernel(const float* __restrict__ x)
{
    const int GELEMS = 16 * NPIX;   // 65536
    size_t base = (size_t)blockIdx.x * GELEMS;
    const float4* xp = (const float4*)(x + base);
    int tid = threadIdx.x;

    float s = 0.f, ss = 0.f;
    for (int i = tid; i < GELEMS / 4; i += 256) {
        float4 vv = xp[i];
        s  += vv.x + vv.y + vv.z + vv.w;
        ss += vv.x * vv.x + vv.y * vv.y + vv.z * vv.z + vv.w * vv.w;
    }
    __shared__ float rs[256], rq[256];
    rs[tid] = s; rq[tid] = ss;
    __syncthreads();
    for (int o = 128; o > 0; o >>= 1) {
        if (tid < o) { rs[tid] += rs[tid + o]; rq[tid] += rq[tid + o]; }
        __syncthreads();
    }
    if (tid == 0) {
        float mean = rs[0] * (1.f / GELEMS);
        float var  = rq[0] * (1.f / GELEMS) - mean * mean;
        g_stats[blockIdx.x] = make_float2(mean, rsqrtf(var + 1e-6f));
    }
}

// ---------------- GroupNorm apply + transpose: x[b,c,hw] -> hnT[b,hw,c] ----------------
__global__ void __launch_bounds__(256) gn_tr_kernel(
    const float* __restrict__ x, const float* __restrict__ gamma,
    const float* __restrict__ beta, float* __restrict__ hnT)
{
    __shared__ float ts[32][33];
    int b = blockIdx.z, ch0 = blockIdx.y << 5, px0 = blockIdx.x << 5;
    int tid = threadIdx.x;
    int cl = tid >> 3, f4 = tid & 7;
    int ch = ch0 + cl;
    float2 st = g_stats[(b << 5) + (ch >> 4)];
    float ga = gamma[ch] * st.y;
    float be = beta[ch] - st.x * ga;
    const float* xp = x + (size_t)b * CCH * NPIX + (size_t)ch * NPIX + px0 + (f4 << 2);
    float4 v = *(const float4*)xp;
    ts[cl][(f4 << 2) + 0] = v.x * ga + be;
    ts[cl][(f4 << 2) + 1] = v.y * ga + be;
    ts[cl][(f4 << 2) + 2] = v.z * ga + be;
    ts[cl][(f4 << 2) + 3] = v.w * ga + be;
    __syncthreads();
    int pl = tid >> 3, c4 = tid & 7;
    float4 o;
    o.x = ts[(c4 << 2) + 0][pl];
    o.y = ts[(c4 << 2) + 1][pl];
    o.z = ts[(c4 << 2) + 2][pl];
    o.w = ts[(c4 << 2) + 3][pl];
    float* hp = hnT + (size_t)b * NPIX * CCH + (size_t)(px0 + pl) * CCH + ch0 + (c4 << 2);
    *(float4*)hp = o;
}

// ---------------- tf32 mma.sync GEMM: D[M,N] = scale*A[M,K]*B[N,K]^T (+bias)(+resid) ----------------
// 128x128 tile, BK=32, 8 warps (2x4), warp tile 64x32, m16n8k8.
// Fragment-ready smem: A subtile 16x8 -> 128 floats lane-major (stride 132),
//                      B subtile  8x8 ->  64 floats lane-major (stride  66).
#define A_SUB 132
#define B_SUB 66
#define BUF_FLOATS 4224                  // 32 subtiles * 132 == 64 subtiles * 66
#define SMEM_GEMM (4 * BUF_FLOATS * 4)   // A0,B0,A1,B1 = 67584 bytes

__global__ void __launch_bounds__(256, 1) gemm_tc(
    const float* __restrict__ A, int lda, long long sA,
    const float* __restrict__ B, int ldb, long long sB,
    float* __restrict__ D, int ldd, long long sD,
    const float* __restrict__ bias, int bias_mode,   // 0 none, 1 per-M-row, 2 per-N-col
    const float* __restrict__ resid, float scale, int K)
{
    extern __shared__ float smem[];
    float* bufA[2] = { smem,                  smem + 2 * BUF_FLOATS };
    float* bufB[2] = { smem + BUF_FLOATS,     smem + 3 * BUF_FLOATS };

    int tid = threadIdx.x, wid = tid >> 5, lane = tid & 31;
    int row0 = blockIdx.y << 7, col0 = blockIdx.x << 7, z = blockIdx.z;

    A += (size_t)z * sA + (size_t)row0 * lda;
    B += (size_t)z * sB + (size_t)col0 * ldb;
    D += (size_t)z * sD;
    if (resid) resid += (size_t)z * sD;

    // staging thread mapping: idx = tid + 256*i, row = idx>>3, c0 = (idx&7)*4
    const int r_   = tid >> 3;          // 0..31 (base row; +32 per i)
    const int c0_  = (tid & 7) << 2;    // 0..28
    const int kt_  = c0_ >> 3;
    // A store offsets (per i)
    int offA[4], offB[4];
#pragma unroll
    for (int i = 0; i < 4; i++) {
        int r = r_ + (i << 5);
        int mt = r >> 4, rr = r & 15;
        int regA = (((c0_ & 7) >= 4) ? 2 : 0) + ((rr >> 3) & 1);
        offA[i] = (mt * 4 + kt_) * A_SUB + ((rr & 7) << 4) + regA;   // + 4*j per element
        int nt = r >> 3, nn = r & 7;
        int regB = ((c0_ & 7) >= 4) ? 1 : 0;
        offB[i] = (nt * 4 + kt_) * B_SUB + (nn << 3) + regB;          // + 2*j per element
    }
    const float* aG = A + (size_t)r_ * lda + c0_;
    const float* bG = B + (size_t)r_ * ldb + c0_;
    const size_t aStep = (size_t)32 * lda;   // per i
    const size_t bStep = (size_t)32 * ldb;

    const int wm4 = (wid & 1) * 4;    // warp M sub-tile base (of 8)
    const int wn4 = (wid >> 1) * 4;   // warp N sub-tile base (of 16)

    float acc[4][4][4];
#pragma unroll
    for (int mt = 0; mt < 4; mt++)
#pragma unroll
        for (int nt = 0; nt < 4; nt++)
#pragma unroll
            for (int rgi = 0; rgi < 4; rgi++) acc[mt][nt][rgi] = 0.f;

    const int NK = K >> 5;
    float4 ra[4], rb[4];

    // prologue: load + store stage 0
#pragma unroll
    for (int i = 0; i < 4; i++) {
        ra[i] = *(const float4*)(aG + i * aStep);
        rb[i] = *(const float4*)(bG + i * bStep);
    }
#pragma unroll
    for (int i = 0; i < 4; i++) {
        float* sa = bufA[0] + offA[i];
        sa[0] = tf32r(ra[i].x); sa[4] = tf32r(ra[i].y); sa[8] = tf32r(ra[i].z); sa[12] = tf32r(ra[i].w);
        float* sb = bufB[0] + offB[i];
        sb[0] = tf32r(rb[i].x); sb[2] = tf32r(rb[i].y); sb[4] = tf32r(rb[i].z); sb[6] = tf32r(rb[i].w);
    }
    __syncthreads();

    for (int s = 0; s < NK; s++) {
        // prefetch next stage into registers
        if (s + 1 < NK) {
            const float* aN = aG + (size_t)(s + 1) * 32;
            const float* bN = bG + (size_t)(s + 1) * 32;
#pragma unroll
            for (int i = 0; i < 4; i++) {
                ra[i] = *(const float4*)(aN + i * aStep);
                rb[i] = *(const float4*)(bN + i * bStep);
            }
        }
        // compute current stage
        const float* cA = bufA[s & 1];
        const float* cB = bufB[s & 1];
#pragma unroll
        for (int kt = 0; kt < 4; kt++) {
            uint4 af[4]; uint2 bf[4];
#pragma unroll
            for (int mt = 0; mt < 4; mt++)
                af[mt] = *(const uint4*)(cA + ((wm4 + mt) * 4 + kt) * A_SUB + (lane << 2));
#pragma unroll
            for (int nt = 0; nt < 4; nt++)
                bf[nt] = *(const uint2*)(cB + ((wn4 + nt) * 4 + kt) * B_SUB + (lane << 1));
#pragma unroll
            for (int mt = 0; mt < 4; mt++)
#pragma unroll
                for (int nt = 0; nt < 4; nt++)
                    mma_tf32_16x8x8(acc[mt][nt], &af[mt].x, &bf[nt].x);
        }
        // stage next
        if (s + 1 < NK) {
            float* dA = bufA[(s + 1) & 1];
            float* dB = bufB[(s + 1) & 1];
#pragma unroll
            for (int i = 0; i < 4; i++) {
                float* sa = dA + offA[i];
                sa[0] = tf32r(ra[i].x); sa[4] = tf32r(ra[i].y); sa[8] = tf32r(ra[i].z); sa[12] = tf32r(ra[i].w);
                float* sb = dB + offB[i];
                sb[0] = tf32r(rb[i].x); sb[2] = tf32r(rb[i].y); sb[4] = tf32r(rb[i].z); sb[6] = tf32r(rb[i].w);
            }
            __syncthreads();
        }
    }

    // ---------------- epilogue ----------------
    const int lane4 = lane >> 2, laneq = lane & 3;
    const int wrow = row0 + (wid & 1) * 64;
    const int wcol = col0 + (wid >> 1) * 32;
#pragma unroll
    for (int mt = 0; mt < 4; mt++) {
#pragma unroll
        for (int half = 0; half < 2; half++) {
            int r = wrow + mt * 16 + lane4 + half * 8;
            float rb_ = (bias_mode == 1) ? bias[r] : 0.f;
            float* drow = D + (size_t)r * ldd + wcol;
            const float* rrow = resid ? (resid + (size_t)r * ldd + wcol) : nullptr;
#pragma unroll
            for (int nt = 0; nt < 4; nt++) {
                int c = nt * 8 + laneq * 2;
                float2 o;
                o.x = acc[mt][nt][half * 2 + 0] * scale + rb_;
                o.y = acc[mt][nt][half * 2 + 1] * scale + rb_;
                if (bias_mode == 2) { o.x += bias[wcol + c]; o.y += bias[wcol + c + 1]; }
                if (rrow) { o.x += rrow[c]; o.y += rrow[c + 1]; }
                *(float2*)(drow + c) = o;
            }
        }
    }
}

// ---------------- Softmax over rows of 512, one warp per row ----------------
__global__ void softmax_kernel(float* __restrict__ attn)
{
    int gw = (blockIdx.x * blockDim.x + threadIdx.x) >> 5;
    int lane = threadIdx.x & 31;
    if (gw >= BATCH * CCH) return;
    float* row = attn + (size_t)gw * CCH;
    float v[16];
    float m = -3.4e38f;
#pragma unroll
    for (int i = 0; i < 16; i++) { v[i] = row[lane + (i << 5)]; m = fmaxf(m, v[i]); }
#pragma unroll
    for (int o = 16; o > 0; o >>= 1) m = fmaxf(m, __shfl_xor_sync(0xffffffffu, m, o));
    float s = 0.f;
#pragma unroll
    for (int i = 0; i < 16; i++) { v[i] = __expf(v[i] - m); s += v[i]; }
#pragma unroll
    for (int o = 16; o > 0; o >>= 1) s += __shfl_xor_sync(0xffffffffu, s, o);
    float inv = 1.f / s;
#pragma unroll
    for (int i = 0; i < 16; i++) row[lane + (i << 5)] = v[i] * inv;
}

// ---------------- launch ----------------
extern "C" void kernel_launch(void* const* d_in, const int* in_sizes, int n_in,
                              void* d_out, int out_size)
{
    const float* x     = (const float*)d_in[0];
    const float* gamma = (const float*)d_in[1];
    const float* beta  = (const float*)d_in[2];
    const float* Wq    = (const float*)d_in[3];
    const float* bq    = (const float*)d_in[4];
    const float* Wk    = (const float*)d_in[5];
    const float* bk    = (const float*)d_in[6];
    const float* Wv    = (const float*)d_in[7];
    const float* bv    = (const float*)d_in[8];
    const float* Wo    = (const float*)d_in[9];
    const float* bo    = (const float*)d_in[10];
    float* out = (float*)d_out;

    float *hnT, *q, *k, *vT, *oT, *attn;
    cudaGetSymbolAddress((void**)&hnT,  g_hnT);
    cudaGetSymbolAddress((void**)&q,    g_q);
    cudaGetSymbolAddress((void**)&k,    g_k);
    cudaGetSymbolAddress((void**)&vT,   g_vT);
    cudaGetSymbolAddress((void**)&oT,   g_oT);
    cudaGetSymbolAddress((void**)&attn, g_attn);

    cudaFuncSetAttribute(gemm_tc, cudaFuncAttributeMaxDynamicSharedMemorySize, SMEM_GEMM);

    const long long sF  = (long long)CCH * NPIX;
    const long long sAt = (long long)CCH * CCH;
    const float scale = 1.0f / sqrtf((float)CCH);

    // 1) GroupNorm stats + apply/transpose -> hnT [b, pixel, channel]
    gn_stats_kernel<<<BATCH * 32, 256>>>(x);
    gn_tr_kernel<<<dim3(NPIX / 32, CCH / 32, BATCH), 256>>>(x, gamma, beta, hnT);

    // 2) q,k [c,p]: D = W (M=512,K=512) x hnT (N=4096,K=512)^T + b
    dim3 gQ(NPIX / 128, CCH / 128, BATCH);
    gemm_tc<<<gQ, 256, SMEM_GEMM>>>(Wq, CCH, 0, hnT, CCH, sF, q, NPIX, sF, bq, 1, nullptr, 1.f, CCH);
    gemm_tc<<<gQ, 256, SMEM_GEMM>>>(Wk, CCH, 0, hnT, CCH, sF, k, NPIX, sF, bk, 1, nullptr, 1.f, CCH);

    // 3) vT [p,c]: D = hnT (M=4096,K=512) x Wv (N=512,K=512)^T + bv (per-col)
    dim3 gV(CCH / 128, NPIX / 128, BATCH);
    gemm_tc<<<gV, 256, SMEM_GEMM>>>(hnT, CCH, sF, Wv, CCH, 0, vT, CCH, sF, bv, 2, nullptr, 1.f, CCH);

    // 4) scores [c,d] = q (M=512,K=4096) x k (N=512,K=4096)^T * c^-0.5
    dim3 gS(CCH / 128, CCH / 128, BATCH);
    gemm_tc<<<gS, 256, SMEM_GEMM>>>(q, NPIX, sF, k, NPIX, sF, attn, CCH, sAt, nullptr, 0, nullptr, scale, NPIX);

    // 5) softmax rows
    softmax_kernel<<<(BATCH * CCH * 32) / 256, 256>>>(attn);

    // 6) oT [p,c] = vT (M=4096,K=512) x attn (N=512,K=512)^T
    gemm_tc<<<gV, 256, SMEM_GEMM>>>(vT, CCH, sF, attn, CCH, sAt, oT, CCH, sF, nullptr, 0, nullptr, 1.f, CCH);

    // 7) final [c,p] = Wo (M=512,K=512) x oT (N=4096,K=512)^T + bo + x
    gemm_tc<<<gQ, 256, SMEM_GEMM>>>(Wo, CCH, 0, oT, CCH, sF, out, NPIX, sF, bo, 1, x, 1.f, CCH);
}

// round 4
// speedup vs baseline: 5.4057x; 2.0142x over previous
#include <cuda_runtime.h>
#include <math.h>
#include <stdint.h>

#define BATCH 16
#define CCH   512
#define NPIX  4096

// ---------------- scratch (__device__ globals; no allocation allowed) ----------------
__device__ float g_hn  [(size_t)BATCH * CCH * NPIX];   // normalized, [b, c, pixel]
__device__ float g_hnT [(size_t)BATCH * NPIX * CCH];   // [b, pixel, c]
__device__ float g_G   [(size_t)BATCH * CCH * CCH];
__device__ float g_T1  [(size_t)BATCH * CCH * CCH];
__device__ float g_S   [(size_t)BATCH * CCH * CCH];
__device__ float g_attn[(size_t)BATCH * CCH * CCH];
__device__ float g_attnT[(size_t)BATCH * CCH * CCH];
__device__ float g_T2  [(size_t)BATCH * CCH * CCH];
__device__ float g_P   [(size_t)BATCH * CCH * CCH];
__device__ float g_WvT [(size_t)CCH * CCH];
__device__ float g_hs  [BATCH * CCH];
__device__ float g_u   [BATCH * CCH];
__device__ float g_w   [BATCH * CCH];
__device__ float g_t   [BATCH * CCH];
__device__ float g_r   [BATCH * CCH];
__device__ float2 g_stats[BATCH * 32];                 // mean, rstd per (b, group)

__device__ __forceinline__ float tf32r(float x) {   // round-to-nearest tf32
    float y; asm("cvt.rna.tf32.f32 %0, %1;" : "=f"(y) : "f"(x)); return y;
}

__device__ __forceinline__ void mma_tf32_16x8x8(float* d, const uint32_t* a, const uint32_t* b) {
    asm volatile(
        "mma.sync.aligned.m16n8k8.row.col.f32.tf32.tf32.f32 "
        "{%0,%1,%2,%3}, {%4,%5,%6,%7}, {%8,%9}, {%0,%1,%2,%3};"
        : "+f"(d[0]), "+f"(d[1]), "+f"(d[2]), "+f"(d[3])
        : "r"(a[0]), "r"(a[1]), "r"(a[2]), "r"(a[3]), "r"(b[0]), "r"(b[1]));
}

// ---------------- GroupNorm stats: one block per (batch, group) ----------------
__global__ void gn_stats_kernel(const float* __restrict__ x)
{
    const int GELEMS = 16 * NPIX;   // 65536
    size_t base = (size_t)blockIdx.x * GELEMS;
    const float4* xp = (const float4*)(x + base);
    int tid = threadIdx.x;

    float s = 0.f, ss = 0.f;
    for (int i = tid; i < GELEMS / 4; i += 256) {
        float4 vv = xp[i];
        s  += vv.x + vv.y + vv.z + vv.w;
        ss += vv.x * vv.x + vv.y * vv.y + vv.z * vv.z + vv.w * vv.w;
    }
    __shared__ float rs[256], rq[256];
    rs[tid] = s; rq[tid] = ss;
    __syncthreads();
    for (int o = 128; o > 0; o >>= 1) {
        if (tid < o) { rs[tid] += rs[tid + o]; rq[tid] += rq[tid + o]; }
        __syncthreads();
    }
    if (tid == 0) {
        float mean = rs[0] * (1.f / GELEMS);
        float var  = rq[0] * (1.f / GELEMS) - mean * mean;
        g_stats[blockIdx.x] = make_float2(mean, rsqrtf(var + 1e-6f));
    }
}

// ---------------- GroupNorm apply: x[b,c,hw] -> hn (same layout) + hnT[b,hw,c] ----------------
__global__ void __launch_bounds__(256) gn_tr_kernel(
    const float* __restrict__ x, const float* __restrict__ gamma,
    const float* __restrict__ beta, float* __restrict__ hn, float* __restrict__ hnT)
{
    __shared__ float ts[32][33];
    int b = blockIdx.z, ch0 = blockIdx.y << 5, px0 = blockIdx.x << 5;
    int tid = threadIdx.x;
    int cl = tid >> 3, f4 = tid & 7;
    int ch = ch0 + cl;
    float2 st = g_stats[(b << 5) + (ch >> 4)];
    float ga = gamma[ch] * st.y;
    float be = beta[ch] - st.x * ga;
    size_t off = (size_t)b * CCH * NPIX + (size_t)ch * NPIX + px0 + (f4 << 2);
    float4 v = *(const float4*)(x + off);
    v.x = v.x * ga + be; v.y = v.y * ga + be;
    v.z = v.z * ga + be; v.w = v.w * ga + be;
    *(float4*)(hn + off) = v;
    ts[cl][(f4 << 2) + 0] = v.x;
    ts[cl][(f4 << 2) + 1] = v.y;
    ts[cl][(f4 << 2) + 2] = v.z;
    ts[cl][(f4 << 2) + 3] = v.w;
    __syncthreads();
    int pl = tid >> 3, c4 = tid & 7;
    float4 o;
    o.x = ts[(c4 << 2) + 0][pl];
    o.y = ts[(c4 << 2) + 1][pl];
    o.z = ts[(c4 << 2) + 2][pl];
    o.w = ts[(c4 << 2) + 3][pl];
    float* hp = hnT + (size_t)b * NPIX * CCH + (size_t)(px0 + pl) * CCH + ch0 + (c4 << 2);
    *(float4*)hp = o;
}

// ---------------- tf32 mma.sync GEMM: D[M,N] = scale*A[M,K]*B[N,K]^T (+bias)(+resid) ----------------
// 128x128 tile, BK=32, 8 warps (2x4), warp tile 64x32, m16n8k8.
// SPLIT=true: 3x-tf32 (hi/lo planes) for near-fp32 accuracy.
#define A_SUB 132
#define B_SUB 66
#define BUF_FLOATS 4224
#define SMEM_PLAIN (4 * BUF_FLOATS * 4)   // 67584 B
#define SMEM_SPLIT (8 * BUF_FLOATS * 4)   // 135168 B

template<bool SPLIT>
__global__ void __launch_bounds__(256, 1) gemm_tc(
    const float* __restrict__ A, int lda, long long sA,
    const float* __restrict__ B, int ldb, long long sB,
    float* __restrict__ D, int ldd, long long sD,
    const float* __restrict__ bias, int bias_mode, long long sBias,  // 0 none, 1 per-M-row, 2 per-N-col
    const float* __restrict__ resid, float scale, int K)
{
    extern __shared__ float smem[];
    const int STAGE_FLOATS = (SPLIT ? 4 : 2) * BUF_FLOATS;

    int tid = threadIdx.x, wid = tid >> 5, lane = tid & 31;
    int row0 = blockIdx.y << 7, col0 = blockIdx.x << 7, z = blockIdx.z;

    A += (size_t)z * sA + (size_t)row0 * lda;
    B += (size_t)z * sB + (size_t)col0 * ldb;
    D += (size_t)z * sD;
    if (resid) resid += (size_t)z * sD;

    const int r_   = tid >> 3;
    const int c0_  = (tid & 7) << 2;
    const int kt_  = c0_ >> 3;
    int offA[4], offB[4];
#pragma unroll
    for (int i = 0; i < 4; i++) {
        int r = r_ + (i << 5);
        int mt = r >> 4, rr = r & 15;
        int regA = (((c0_ & 7) >= 4) ? 2 : 0) + ((rr >> 3) & 1);
        offA[i] = (mt * 4 + kt_) * A_SUB + ((rr & 7) << 4) + regA;
        int nt = r >> 3, nn = r & 7;
        int regB = ((c0_ & 7) >= 4) ? 1 : 0;
        offB[i] = (nt * 4 + kt_) * B_SUB + (nn << 3) + regB;
    }
    const float* aG = A + (size_t)r_ * lda + c0_;
    const float* bG = B + (size_t)r_ * ldb + c0_;
    const size_t aStep = (size_t)32 * lda;
    const size_t bStep = (size_t)32 * ldb;

    const int wm4 = (wid & 1) * 4;
    const int wn4 = (wid >> 1) * 4;

    float acc[4][4][4];
#pragma unroll
    for (int mt = 0; mt < 4; mt++)
#pragma unroll
        for (int nt = 0; nt < 4; nt++)
#pragma unroll
            for (int rgi = 0; rgi < 4; rgi++) acc[mt][nt][rgi] = 0.f;

    const int NK = K >> 5;
    float4 ra[4], rb[4];

    // staging store helper (hi + optional lo planes)
    auto stage_store = [&](float* base, int i) {
        float* sa  = base + offA[i];
        float* sb  = base + BUF_FLOATS + offB[i];
        float h;
        h = tf32r(ra[i].x); sa[0]  = h; if (SPLIT) (base + 2*BUF_FLOATS + offA[i])[0]  = tf32r(ra[i].x - h);
        h = tf32r(ra[i].y); sa[4]  = h; if (SPLIT) (base + 2*BUF_FLOATS + offA[i])[4]  = tf32r(ra[i].y - h);
        h = tf32r(ra[i].z); sa[8]  = h; if (SPLIT) (base + 2*BUF_FLOATS + offA[i])[8]  = tf32r(ra[i].z - h);
        h = tf32r(ra[i].w); sa[12] = h; if (SPLIT) (base + 2*BUF_FLOATS + offA[i])[12] = tf32r(ra[i].w - h);
        h = tf32r(rb[i].x); sb[0]  = h; if (SPLIT) (base + 3*BUF_FLOATS + offB[i])[0]  = tf32r(rb[i].x - h);
        h = tf32r(rb[i].y); sb[2]  = h; if (SPLIT) (base + 3*BUF_FLOATS + offB[i])[2]  = tf32r(rb[i].y - h);
        h = tf32r(rb[i].z); sb[4]  = h; if (SPLIT) (base + 3*BUF_FLOATS + offB[i])[4]  = tf32r(rb[i].z - h);
        h = tf32r(rb[i].w); sb[6]  = h; if (SPLIT) (base + 3*BUF_FLOATS + offB[i])[6]  = tf32r(rb[i].w - h);
    };

    // prologue: load + store stage 0
#pragma unroll
    for (int i = 0; i < 4; i++) {
        ra[i] = *(const float4*)(aG + i * aStep);
        rb[i] = *(const float4*)(bG + i * bStep);
    }
#pragma unroll
    for (int i = 0; i < 4; i++) stage_store(smem, i);
    __syncthreads();

    for (int s = 0; s < NK; s++) {
        if (s + 1 < NK) {
            const float* aN = aG + (size_t)(s + 1) * 32;
            const float* bN = bG + (size_t)(s + 1) * 32;
#pragma unroll
            for (int i = 0; i < 4; i++) {
                ra[i] = *(const float4*)(aN + i * aStep);
                rb[i] = *(const float4*)(bN + i * bStep);
            }
        }
        const float* cS = smem + (s & 1) * STAGE_FLOATS;
#pragma unroll
        for (int kt = 0; kt < 4; kt++) {
            uint4 af[4]; uint2 bf[4];
#pragma unroll
            for (int mt = 0; mt < 4; mt++)
                af[mt] = *(const uint4*)(cS + ((wm4 + mt) * 4 + kt) * A_SUB + (lane << 2));
#pragma unroll
            for (int nt = 0; nt < 4; nt++)
                bf[nt] = *(const uint2*)(cS + BUF_FLOATS + ((wn4 + nt) * 4 + kt) * B_SUB + (lane << 1));
#pragma unroll
            for (int mt = 0; mt < 4; mt++)
#pragma unroll
                for (int nt = 0; nt < 4; nt++)
                    mma_tf32_16x8x8(acc[mt][nt], &af[mt].x, &bf[nt].x);
            if (SPLIT) {
                uint4 al[4]; uint2 bl[4];
#pragma unroll
                for (int mt = 0; mt < 4; mt++)
                    al[mt] = *(const uint4*)(cS + 2*BUF_FLOATS + ((wm4 + mt) * 4 + kt) * A_SUB + (lane << 2));
#pragma unroll
                for (int nt = 0; nt < 4; nt++)
                    bl[nt] = *(const uint2*)(cS + 3*BUF_FLOATS + ((wn4 + nt) * 4 + kt) * B_SUB + (lane << 1));
#pragma unroll
                for (int mt = 0; mt < 4; mt++)
#pragma unroll
                    for (int nt = 0; nt < 4; nt++) {
                        mma_tf32_16x8x8(acc[mt][nt], &af[mt].x, &bl[nt].x);
                        mma_tf32_16x8x8(acc[mt][nt], &al[mt].x, &bf[nt].x);
                    }
            }
        }
        if (s + 1 < NK) {
            float* dS = smem + ((s + 1) & 1) * STAGE_FLOATS;
#pragma unroll
            for (int i = 0; i < 4; i++) stage_store(dS, i);
            __syncthreads();
        }
    }

    // ---------------- epilogue ----------------
    const int lane4 = lane >> 2, laneq = lane & 3;
    const int wrow = row0 + (wid & 1) * 64;
    const int wcol = col0 + (wid >> 1) * 32;
#pragma unroll
    for (int mt = 0; mt < 4; mt++) {
#pragma unroll
        for (int half = 0; half < 2; half++) {
            int r = wrow + mt * 16 + lane4 + half * 8;
            float rb_ = (bias_mode == 1) ? bias[(size_t)z * sBias + r] : 0.f;
            float* drow = D + (size_t)r * ldd + wcol;
            const float* rrow = resid ? (resid + (size_t)r * ldd + wcol) : nullptr;
#pragma unroll
            for (int nt = 0; nt < 4; nt++) {
                int c = nt * 8 + laneq * 2;
                float2 o;
                o.x = acc[mt][nt][half * 2 + 0] * scale + rb_;
                o.y = acc[mt][nt][half * 2 + 1] * scale + rb_;
                if (bias_mode == 2) {
                    o.x += bias[(size_t)z * sBias + wcol + c];
                    o.y += bias[(size_t)z * sBias + wcol + c + 1];
                }
                if (rrow) { o.x += rrow[c]; o.y += rrow[c + 1]; }
                *(float2*)(drow + c) = o;
            }
        }
    }
}

// ---------------- softmax with rank-1 bias corrections ----------------
// attn[c,:] = softmax(scale * (S[c,:] + u[c]*bk[:] + bq[c]*w[:] + NPIX*bq[c]*bk[:]))
__global__ void softmax_kernel(const float* __restrict__ S, float* __restrict__ attn,
                               const float* __restrict__ u, const float* __restrict__ w,
                               const float* __restrict__ bq, const float* __restrict__ bk,
                               float scale)
{
    int gw = (blockIdx.x * blockDim.x + threadIdx.x) >> 5;
    int lane = threadIdx.x & 31;
    if (gw >= BATCH * CCH) return;
    int b = gw >> 9, c = gw & 511;
    const float* row = S + (size_t)gw * CCH;
    float* orow = attn + (size_t)gw * CCH;
    float uc = u[(b << 9) + c], bqc = bq[c];
    float v[16];
    float m = -3.4e38f;
#pragma unroll
    for (int i = 0; i < 16; i++) {
        int d = lane + (i << 5);
        float bkd = bk[d], wd = w[(b << 9) + d];
        v[i] = scale * (row[d] + uc * bkd + bqc * wd + (float)NPIX * bqc * bkd);
        m = fmaxf(m, v[i]);
    }
#pragma unroll
    for (int o = 16; o > 0; o >>= 1) m = fmaxf(m, __shfl_xor_sync(0xffffffffu, m, o));
    float s = 0.f;
#pragma unroll
    for (int i = 0; i < 16; i++) { v[i] = __expf(v[i] - m); s += v[i]; }
#pragma unroll
    for (int o = 16; o > 0; o >>= 1) s += __shfl_xor_sync(0xffffffffu, s, o);
    float inv = 1.f / s;
#pragma unroll
    for (int i = 0; i < 16; i++) orow[lane + (i << 5)] = v[i] * inv;
}

// ---------------- 512x512 transpose (per batch z) ----------------
__global__ void __launch_bounds__(256) transpose_kernel(
    const float* __restrict__ in, float* __restrict__ out, long long sIn, long long sOut)
{
    __shared__ float t[32][33];
    int z = blockIdx.z;
    in  += (size_t)z * sIn;
    out += (size_t)z * sOut;
    int x0 = blockIdx.x << 5, y0 = blockIdx.y << 5;
    int lx = threadIdx.x & 31, ly = threadIdx.x >> 5;
#pragma unroll
    for (int i = 0; i < 4; i++)
        t[ly + i * 8][lx] = in[(size_t)(y0 + ly + i * 8) * CCH + x0 + lx];
    __syncthreads();
#pragma unroll
    for (int i = 0; i < 4; i++)
        out[(size_t)(x0 + ly + i * 8) * CCH + y0 + lx] = t[lx][ly + i * 8];
}

// ---------------- row sums of hn: hs[b,c] = sum_n hn[b,c,n] ----------------
__global__ void hs_kernel(const float* __restrict__ hn, float* __restrict__ hs)
{
    int gw = (blockIdx.x * blockDim.x + threadIdx.x) >> 5;
    int lane = threadIdx.x & 31;
    if (gw >= BATCH * CCH) return;
    const float* row = hn + (size_t)gw * NPIX;
    float s = 0.f;
    for (int i = lane; i < NPIX; i += 32) s += row[i];
#pragma unroll
    for (int o = 16; o > 0; o >>= 1) s += __shfl_xor_sync(0xffffffffu, s, o);
    if (lane == 0) hs[gw] = s;
}

// ---------------- batched matvec: y[b,m] = sum_k W[b*sW + m*512 + k] * v[b*sV + k] (+bias[m]) ----------------
__global__ void matvec_kernel(const float* __restrict__ W, long long sW,
                              const float* __restrict__ v, long long sV,
                              float* __restrict__ y, long long sY,
                              const float* __restrict__ bias)
{
    int b = blockIdx.y;
    int m = (blockIdx.x << 3) + (threadIdx.x >> 5);
    int lane = threadIdx.x & 31;
    const float* wr = W + (size_t)b * sW + (size_t)m * CCH;
    const float* vv = v + (size_t)b * sV;
    float s = 0.f;
    for (int k = lane; k < CCH; k += 32) s += wr[k] * vv[k];
#pragma unroll
    for (int o = 16; o > 0; o >>= 1) s += __shfl_xor_sync(0xffffffffu, s, o);
    if (lane == 0) y[(size_t)b * sY + m] = s + (bias ? bias[m] : 0.f);
}

// ---------------- launch ----------------
extern "C" void kernel_launch(void* const* d_in, const int* in_sizes, int n_in,
                              void* d_out, int out_size)
{
    const float* x     = (const float*)d_in[0];
    const float* gamma = (const float*)d_in[1];
    const float* beta  = (const float*)d_in[2];
    const float* Wq    = (const float*)d_in[3];
    const float* bq    = (const float*)d_in[4];
    const float* Wk    = (const float*)d_in[5];
    const float* bk    = (const float*)d_in[6];
    const float* Wv    = (const float*)d_in[7];
    const float* bv    = (const float*)d_in[8];
    const float* Wo    = (const float*)d_in[9];
    const float* bo    = (const float*)d_in[10];
    float* out = (float*)d_out;

    float *hn, *hnT, *G, *T1, *S, *attn, *attnT, *T2, *P, *WvT, *hs, *u, *w, *t, *r;
    cudaGetSymbolAddress((void**)&hn,    g_hn);
    cudaGetSymbolAddress((void**)&hnT,   g_hnT);
    cudaGetSymbolAddress((void**)&G,     g_G);
    cudaGetSymbolAddress((void**)&T1,    g_T1);
    cudaGetSymbolAddress((void**)&S,     g_S);
    cudaGetSymbolAddress((void**)&attn,  g_attn);
    cudaGetSymbolAddress((void**)&attnT, g_attnT);
    cudaGetSymbolAddress((void**)&T2,    g_T2);
    cudaGetSymbolAddress((void**)&P,     g_P);
    cudaGetSymbolAddress((void**)&WvT,   g_WvT);
    cudaGetSymbolAddress((void**)&hs,    g_hs);
    cudaGetSymbolAddress((void**)&u,     g_u);
    cudaGetSymbolAddress((void**)&w,     g_w);
    cudaGetSymbolAddress((void**)&t,     g_t);
    cudaGetSymbolAddress((void**)&r,     g_r);

    cudaFuncSetAttribute(gemm_tc<false>, cudaFuncAttributeMaxDynamicSharedMemorySize, SMEM_PLAIN);
    cudaFuncSetAttribute(gemm_tc<true>,  cudaFuncAttributeMaxDynamicSharedMemorySize, SMEM_SPLIT);

    const long long sF  = (long long)CCH * NPIX;
    const long long sAt = (long long)CCH * CCH;
    const float scale = 1.0f / sqrtf((float)CCH);

    // 1) GroupNorm -> hn + hnT; row sums; bias-correction vectors; WvT
    gn_stats_kernel<<<BATCH * 32, 256>>>(x);
    gn_tr_kernel<<<dim3(NPIX / 32, CCH / 32, BATCH), 256>>>(x, gamma, beta, hn, hnT);
    hs_kernel<<<(BATCH * CCH * 32) / 256, 256>>>(hn, hs);
    matvec_kernel<<<dim3(CCH / 8, BATCH), 256>>>(Wq, 0, hs, CCH, u, CCH, nullptr);
    matvec_kernel<<<dim3(CCH / 8, BATCH), 256>>>(Wk, 0, hs, CCH, w, CCH, nullptr);
    transpose_kernel<<<dim3(16, 16, 1), 256>>>(Wv, WvT, 0, 0);

    // 2) G = hn hn^T   [512,512] per batch, K=4096  (heavy #1)
    gemm_tc<false><<<dim3(4, 4, BATCH), 256, SMEM_PLAIN>>>(
        hn, NPIX, sF, hn, NPIX, sF, G, CCH, sAt, nullptr, 0, 0, nullptr, 1.f, NPIX);

    // 3) T1 = Wq G (G symmetric); S = T1 Wk^T   (split-tf32 smalls)
    gemm_tc<true><<<dim3(4, 4, BATCH), 256, SMEM_SPLIT>>>(
        Wq, CCH, 0, G, CCH, sAt, T1, CCH, sAt, nullptr, 0, 0, nullptr, 1.f, CCH);
    gemm_tc<true><<<dim3(4, 4, BATCH), 256, SMEM_SPLIT>>>(
        T1, CCH, sAt, Wk, CCH, 0, S, CCH, sAt, nullptr, 0, 0, nullptr, 1.f, CCH);

    // 4) softmax (with exact rank-1 bias corrections), then transpose
    softmax_kernel<<<(BATCH * CCH * 32) / 256, 256>>>(S, attn, u, w, bq, bk, scale);
    transpose_kernel<<<dim3(16, 16, BATCH), 256>>>(attn, attnT, sAt, sAt);

    // 5) T2 = Wo attn (B=attnT); P = T2 Wv (B=WvT)   (split-tf32 smalls)
    gemm_tc<true><<<dim3(4, 4, BATCH), 256, SMEM_SPLIT>>>(
        Wo, CCH, 0, attnT, CCH, sAt, T2, CCH, sAt, nullptr, 0, 0, nullptr, 1.f, CCH);
    gemm_tc<true><<<dim3(4, 4, BATCH), 256, SMEM_SPLIT>>>(
        T2, CCH, sAt, WvT, CCH, 0, P, CCH, sAt, nullptr, 0, 0, nullptr, 1.f, CCH);

    // 6) r = Wo (attn bv) + bo   (per-channel out bias)
    matvec_kernel<<<dim3(CCH / 8, BATCH), 256>>>(attn, sAt, bv, 0, t, CCH, nullptr);
    matvec_kernel<<<dim3(CCH / 8, BATCH), 256>>>(Wo, 0, t, CCH, r, CCH, bo);

    // 7) out = P hn + r + x   [512,4096] per batch, K=512  (heavy #2)
    gemm_tc<false><<<dim3(NPIX / 128, 4, BATCH), 256, SMEM_PLAIN>>>(
        P, CCH, sAt, hnT, CCH, sF, out, NPIX, sF, r, 1, CCH, x, 1.f, CCH);
}

// round 5
// speedup vs baseline: 6.2658x; 1.1591x over previous
#include <cuda_runtime.h>
#include <math.h>
#include <stdint.h>

#define BATCH 16
#define CCH   512
#define NPIX  4096

// ---------------- scratch (__device__ globals; no allocation allowed) ----------------
__device__ float g_hn  [(size_t)BATCH * CCH * NPIX];   // normalized, [b, c, pixel]
__device__ float g_hnT [(size_t)BATCH * NPIX * CCH];   // [b, pixel, c]
__device__ float g_G   [(size_t)BATCH * CCH * CCH];
__device__ float g_T1  [(size_t)BATCH * CCH * CCH];
__device__ float g_S   [(size_t)BATCH * CCH * CCH];
__device__ float g_attn[(size_t)BATCH * CCH * CCH];
__device__ float g_attnT[(size_t)BATCH * CCH * CCH];
__device__ float g_T2  [(size_t)BATCH * CCH * CCH];
__device__ float g_P   [(size_t)BATCH * CCH * CCH];
__device__ float g_WvT [(size_t)CCH * CCH];
__device__ float g_hs  [BATCH * CCH];
__device__ float g_u   [BATCH * CCH];
__device__ float g_w   [BATCH * CCH];
__device__ float g_t   [BATCH * CCH];
__device__ float g_r   [BATCH * CCH];
__device__ float2 g_stats[BATCH * 32];                 // mean, rstd per (b, group)

__device__ __forceinline__ float tf32r(float x) {   // round-to-nearest tf32
    float y; asm("cvt.rna.tf32.f32 %0, %1;" : "=f"(y) : "f"(x)); return y;
}

__device__ __forceinline__ void mma_tf32_16x8x8(float* d, const uint32_t* a, const uint32_t* b) {
    asm volatile(
        "mma.sync.aligned.m16n8k8.row.col.f32.tf32.tf32.f32 "
        "{%0,%1,%2,%3}, {%4,%5,%6,%7}, {%8,%9}, {%0,%1,%2,%3};"
        : "+f"(d[0]), "+f"(d[1]), "+f"(d[2]), "+f"(d[3])
        : "r"(a[0]), "r"(a[1]), "r"(a[2]), "r"(a[3]), "r"(b[0]), "r"(b[1]));
}

// ---------------- GroupNorm stats + per-channel hs: one block per (batch, group) ----------------
// hs[b,c] = sum_n hn[b,c,n] = ga*chsum_x + NPIX*be
__global__ void gn_stats_kernel(const float* __restrict__ x,
                                const float* __restrict__ gamma,
                                const float* __restrict__ beta,
                                float* __restrict__ hs)
{
    int bg = blockIdx.x;
    int b = bg >> 5, g = bg & 31;
    size_t base = (size_t)bg * (16 * NPIX);
    int wid = threadIdx.x >> 5, lane = threadIdx.x & 31;
    __shared__ float chs[16], chss[16];

#pragma unroll
    for (int c2 = 0; c2 < 2; c2++) {
        int cl = wid * 2 + c2;
        const float4* xp = (const float4*)(x + base + (size_t)cl * NPIX);
        float s = 0.f, ss = 0.f;
        for (int i = lane; i < NPIX / 4; i += 32) {
            float4 v = xp[i];
            s  += v.x + v.y + v.z + v.w;
            ss += v.x * v.x + v.y * v.y + v.z * v.z + v.w * v.w;
        }
#pragma unroll
        for (int o = 16; o > 0; o >>= 1) {
            s  += __shfl_xor_sync(0xffffffffu, s, o);
            ss += __shfl_xor_sync(0xffffffffu, ss, o);
        }
        if (lane == 0) { chs[cl] = s; chss[cl] = ss; }
    }
    __syncthreads();
    if (threadIdx.x == 0) {
        float s = 0.f, ss = 0.f;
#pragma unroll
        for (int i = 0; i < 16; i++) { s += chs[i]; ss += chss[i]; }
        float mean = s * (1.f / (16 * NPIX));
        float var  = ss * (1.f / (16 * NPIX)) - mean * mean;
        g_stats[bg] = make_float2(mean, rsqrtf(var + 1e-6f));
    }
    __syncthreads();
    if (threadIdx.x < 16) {
        int cl = threadIdx.x, ch = g * 16 + cl;
        float2 st = g_stats[bg];
        float ga = gamma[ch] * st.y;
        float be = beta[ch] - st.x * ga;
        hs[(b << 9) + ch] = ga * chs[cl] + (float)NPIX * be;
    }
}

// ---------------- GroupNorm apply: x[b,c,hw] -> hn (same layout) + hnT[b,hw,c] ----------------
__global__ void __launch_bounds__(256) gn_tr_kernel(
    const float* __restrict__ x, const float* __restrict__ gamma,
    const float* __restrict__ beta, float* __restrict__ hn, float* __restrict__ hnT)
{
    __shared__ float ts[32][33];
    int b = blockIdx.z, ch0 = blockIdx.y << 5, px0 = blockIdx.x << 5;
    int tid = threadIdx.x;
    int cl = tid >> 3, f4 = tid & 7;
    int ch = ch0 + cl;
    float2 st = g_stats[(b << 5) + (ch >> 4)];
    float ga = gamma[ch] * st.y;
    float be = beta[ch] - st.x * ga;
    size_t off = (size_t)b * CCH * NPIX + (size_t)ch * NPIX + px0 + (f4 << 2);
    float4 v = *(const float4*)(x + off);
    v.x = v.x * ga + be; v.y = v.y * ga + be;
    v.z = v.z * ga + be; v.w = v.w * ga + be;
    *(float4*)(hn + off) = v;
    ts[cl][(f4 << 2) + 0] = v.x;
    ts[cl][(f4 << 2) + 1] = v.y;
    ts[cl][(f4 << 2) + 2] = v.z;
    ts[cl][(f4 << 2) + 3] = v.w;
    __syncthreads();
    int pl = tid >> 3, c4 = tid & 7;
    float4 o;
    o.x = ts[(c4 << 2) + 0][pl];
    o.y = ts[(c4 << 2) + 1][pl];
    o.z = ts[(c4 << 2) + 2][pl];
    o.w = ts[(c4 << 2) + 3][pl];
    float* hp = hnT + (size_t)b * NPIX * CCH + (size_t)(px0 + pl) * CCH + ch0 + (c4 << 2);
    *(float4*)hp = o;
}

// ---------------- tf32 mma.sync GEMM: D[M,N] = scale*A[M,K]*B[N,K]^T (+bias)(+resid) ----------------
// CTA 256x128, BK=32, 8 warps (4x2), warp tile 64x64, m16n8k8.
// SPLIT=true: 3x-tf32 (hi/lo planes) for near-fp32 accuracy.
#define A_SUB 132
#define B_SUB 66
#define A_FLOATS (64 * A_SUB)            // 8448 (16 mt * 4 kt subtiles)
#define B_FLOATS (64 * B_SUB)            // 4224 (16 nt * 4 kt subtiles)
#define STAGE_F (A_FLOATS + B_FLOATS)    // 12672 floats
#define SMEM_PLAIN (2 * STAGE_F * 4)     // 101376 B
#define SMEM_SPLIT (4 * STAGE_F * 4)     // 202752 B

template<bool SPLIT>
__global__ void __launch_bounds__(256, 1) gemm_tc(
    const float* __restrict__ A, int lda, long long sA,
    const float* __restrict__ B, int ldb, long long sB,
    float* __restrict__ D, int ldd, long long sD,
    const float* __restrict__ bias, int bias_mode, long long sBias,  // 0 none, 1 per-M-row, 2 per-N-col
    const float* __restrict__ resid, float scale, int K, int sym)
{
    extern __shared__ float smem[];
    const int BUFSZ = (SPLIT ? 2 : 1) * STAGE_F;

    int tid = threadIdx.x, wid = tid >> 5, lane = tid & 31;
    int z = blockIdx.z;
    int row0, col0;
    if (sym) {   // symmetric 512x512: tiles {(y0:x0,x1), (y1:x0..x3)} over blockIdx.x 0..5
        int t = blockIdx.x;
        row0 = (t < 2) ? 0 : 256;
        col0 = ((t < 2) ? t : (t - 2)) << 7;
    } else {
        row0 = blockIdx.y << 8;
        col0 = blockIdx.x << 7;
    }

    A += (size_t)z * sA + (size_t)row0 * lda;
    B += (size_t)z * sB + (size_t)col0 * ldb;
    D += (size_t)z * sD;
    if (resid) resid += (size_t)z * sD;

    const int r_  = tid >> 3;           // 0..31
    const int c0_ = (tid & 7) << 2;     // 0..28
    const int kt_ = c0_ >> 3;
    int offA[8], offB[4];
#pragma unroll
    for (int i = 0; i < 8; i++) {
        int r = r_ + (i << 5);          // 0..255
        int mt = r >> 4, rr = r & 15;
        int regA = (((c0_ & 7) >= 4) ? 2 : 0) + ((rr >> 3) & 1);
        offA[i] = (mt * 4 + kt_) * A_SUB + ((rr & 7) << 4) + regA;
    }
#pragma unroll
    for (int i = 0; i < 4; i++) {
        int r = r_ + (i << 5);          // 0..127
        int nt = r >> 3, nn = r & 7;
        int regB = ((c0_ & 7) >= 4) ? 1 : 0;
        offB[i] = A_FLOATS + (nt * 4 + kt_) * B_SUB + (nn << 3) + regB;
    }
    const float* aG = A + (size_t)r_ * lda + c0_;
    const float* bG = B + (size_t)r_ * ldb + c0_;
    const size_t aStep = (size_t)32 * lda;
    const size_t bStep = (size_t)32 * ldb;

    const int wm4 = (wid & 3) * 4;      // warp M group (4 mt of 16 rows)
    const int wn8 = (wid >> 2) * 8;     // warp N group (8 nt of 8 cols)

    float acc[4][8][4];
#pragma unroll
    for (int mt = 0; mt < 4; mt++)
#pragma unroll
        for (int nt = 0; nt < 8; nt++)
#pragma unroll
            for (int rgi = 0; rgi < 4; rgi++) acc[mt][nt][rgi] = 0.f;

    const int NK = K >> 5;
    float4 ra[8], rb[4];

    auto stage_load = [&](int s) {
        const float* aN = aG + (size_t)s * 32;
        const float* bN = bG + (size_t)s * 32;
#pragma unroll
        for (int i = 0; i < 8; i++) ra[i] = *(const float4*)(aN + i * aStep);
#pragma unroll
        for (int i = 0; i < 4; i++) rb[i] = *(const float4*)(bN + i * bStep);
    };
    auto stage_store = [&](float* base) {
        float h;
#pragma unroll
        for (int i = 0; i < 8; i++) {
            float* sa = base + offA[i];
            h = tf32r(ra[i].x); sa[0]  = h; if (SPLIT) (base + STAGE_F + offA[i])[0]  = tf32r(ra[i].x - h);
            h = tf32r(ra[i].y); sa[4]  = h; if (SPLIT) (base + STAGE_F + offA[i])[4]  = tf32r(ra[i].y - h);
            h = tf32r(ra[i].z); sa[8]  = h; if (SPLIT) (base + STAGE_F + offA[i])[8]  = tf32r(ra[i].z - h);
            h = tf32r(ra[i].w); sa[12] = h; if (SPLIT) (base + STAGE_F + offA[i])[12] = tf32r(ra[i].w - h);
        }
#pragma unroll
        for (int i = 0; i < 4; i++) {
            float* sb = base + offB[i];
            h = tf32r(rb[i].x); sb[0] = h; if (SPLIT) (base + STAGE_F + offB[i])[0] = tf32r(rb[i].x - h);
            h = tf32r(rb[i].y); sb[2] = h; if (SPLIT) (base + STAGE_F + offB[i])[2] = tf32r(rb[i].y - h);
            h = tf32r(rb[i].z); sb[4] = h; if (SPLIT) (base + STAGE_F + offB[i])[4] = tf32r(rb[i].z - h);
            h = tf32r(rb[i].w); sb[6] = h; if (SPLIT) (base + STAGE_F + offB[i])[6] = tf32r(rb[i].w - h);
        }
    };

    // prologue
    stage_load(0);
    stage_store(smem);
    __syncthreads();

    for (int s = 0; s < NK; s++) {
        if (s + 1 < NK) stage_load(s + 1);
        const float* cS = smem + (s & 1) * BUFSZ;
#pragma unroll
        for (int kt = 0; kt < 4; kt++) {
            uint4 af[4]; uint2 bf[8];
#pragma unroll
            for (int mt = 0; mt < 4; mt++)
                af[mt] = *(const uint4*)(cS + ((wm4 + mt) * 4 + kt) * A_SUB + (lane << 2));
#pragma unroll
            for (int nt = 0; nt < 8; nt++)
                bf[nt] = *(const uint2*)(cS + A_FLOATS + ((wn8 + nt) * 4 + kt) * B_SUB + (lane << 1));
#pragma unroll
            for (int mt = 0; mt < 4; mt++)
#pragma unroll
                for (int nt = 0; nt < 8; nt++)
                    mma_tf32_16x8x8(acc[mt][nt], &af[mt].x, &bf[nt].x);
            if (SPLIT) {
                uint4 al[4]; uint2 bl[8];
#pragma unroll
                for (int mt = 0; mt < 4; mt++)
                    al[mt] = *(const uint4*)(cS + STAGE_F + ((wm4 + mt) * 4 + kt) * A_SUB + (lane << 2));
#pragma unroll
                for (int nt = 0; nt < 8; nt++)
                    bl[nt] = *(const uint2*)(cS + STAGE_F + A_FLOATS + ((wn8 + nt) * 4 + kt) * B_SUB + (lane << 1));
#pragma unroll
                for (int mt = 0; mt < 4; mt++)
#pragma unroll
                    for (int nt = 0; nt < 8; nt++) {
                        mma_tf32_16x8x8(acc[mt][nt], &af[mt].x, &bl[nt].x);
                        mma_tf32_16x8x8(acc[mt][nt], &al[mt].x, &bf[nt].x);
                    }
            }
        }
        if (s + 1 < NK) {
            stage_store(smem + ((s + 1) & 1) * BUFSZ);
            __syncthreads();
        }
    }

    // ---------------- epilogue ----------------
    const int lane4 = lane >> 2, laneq = lane & 3;
    const int wrow = row0 + (wid & 3) * 64;
    const int wcol = col0 + (wid >> 2) * 64;
#pragma unroll
    for (int mt = 0; mt < 4; mt++) {
#pragma unroll
        for (int half = 0; half < 2; half++) {
            int r = wrow + mt * 16 + lane4 + half * 8;
            float rb_ = (bias_mode == 1) ? bias[(size_t)z * sBias + r] : 0.f;
            float* drow = D + (size_t)r * ldd + wcol;
            const float* rrow = resid ? (resid + (size_t)r * ldd + wcol) : nullptr;
#pragma unroll
            for (int nt = 0; nt < 8; nt++) {
                int c = nt * 8 + laneq * 2;
                float2 o;
                o.x = acc[mt][nt][half * 2 + 0] * scale + rb_;
                o.y = acc[mt][nt][half * 2 + 1] * scale + rb_;
                if (bias_mode == 2) {
                    o.x += bias[(size_t)z * sBias + wcol + c];
                    o.y += bias[(size_t)z * sBias + wcol + c + 1];
                }
                if (rrow) { o.x += rrow[c]; o.y += rrow[c + 1]; }
                *(float2*)(drow + c) = o;
            }
        }
    }
}

// ---------------- mirror upper-right block of symmetric G: G[i,j]=G[j,i], i<256<=j ----------------
__global__ void __launch_bounds__(256) mirror_kernel(float* __restrict__ G)
{
    __shared__ float t[32][33];
    float* Gb = G + (size_t)blockIdx.z * CCH * CCH;
    int i0 = blockIdx.y << 5, j0 = 256 + (blockIdx.x << 5);
    int lx = threadIdx.x & 31, ly = threadIdx.x >> 5;
#pragma unroll
    for (int ii = 0; ii < 4; ii++)
        t[ly + ii * 8][lx] = Gb[(size_t)(j0 + ly + ii * 8) * CCH + i0 + lx];
    __syncthreads();
#pragma unroll
    for (int ii = 0; ii < 4; ii++)
        Gb[(size_t)(i0 + ly + ii * 8) * CCH + j0 + lx] = t[lx][ly + ii * 8];
}

// ---------------- softmax with rank-1 bias corrections ----------------
__global__ void softmax_kernel(const float* __restrict__ S, float* __restrict__ attn,
                               const float* __restrict__ u, const float* __restrict__ w,
                               const float* __restrict__ bq, const float* __restrict__ bk,
                               float scale)
{
    int gw = (blockIdx.x * blockDim.x + threadIdx.x) >> 5;
    int lane = threadIdx.x & 31;
    if (gw >= BATCH * CCH) return;
    int b = gw >> 9, c = gw & 511;
    const float* row = S + (size_t)gw * CCH;
    float* orow = attn + (size_t)gw * CCH;
    float uc = u[(b << 9) + c], bqc = bq[c];
    float v[16];
    float m = -3.4e38f;
#pragma unroll
    for (int i = 0; i < 16; i++) {
        int d = lane + (i << 5);
        float bkd = bk[d], wd = w[(b << 9) + d];
        v[i] = scale * (row[d] + uc * bkd + bqc * wd + (float)NPIX * bqc * bkd);
        m = fmaxf(m, v[i]);
    }
#pragma unroll
    for (int o = 16; o > 0; o >>= 1) m = fmaxf(m, __shfl_xor_sync(0xffffffffu, m, o));
    float s = 0.f;
#pragma unroll
    for (int i = 0; i < 16; i++) { v[i] = __expf(v[i] - m); s += v[i]; }
#pragma unroll
    for (int o = 16; o > 0; o >>= 1) s += __shfl_xor_sync(0xffffffffu, s, o);
    float inv = 1.f / s;
#pragma unroll
    for (int i = 0; i < 16; i++) orow[lane + (i << 5)] = v[i] * inv;
}

// ---------------- 512x512 transpose (per batch z) ----------------
__global__ void __launch_bounds__(256) transpose_kernel(
    const float* __restrict__ in, float* __restrict__ out, long long sIn, long long sOut)
{
    __shared__ float t[32][33];
    int z = blockIdx.z;
    in  += (size_t)z * sIn;
    out += (size_t)z * sOut;
    int x0 = blockIdx.x << 5, y0 = blockIdx.y << 5;
    int lx = threadIdx.x & 31, ly = threadIdx.x >> 5;
#pragma unroll
    for (int i = 0; i < 4; i++)
        t[ly + i * 8][lx] = in[(size_t)(y0 + ly + i * 8) * CCH + x0 + lx];
    __syncthreads();
#pragma unroll
    for (int i = 0; i < 4; i++)
        out[(size_t)(x0 + ly + i * 8) * CCH + y0 + lx] = t[lx][ly + i * 8];
}

// ---------------- batched matvec: y[b,m] = W[b] row m . v[b] (+bias[m]) ----------------
__global__ void matvec_kernel(const float* __restrict__ W, long long sW,
                              const float* __restrict__ v, long long sV,
                              float* __restrict__ y, long long sY,
                              const float* __restrict__ bias)
{
    int b = blockIdx.y;
    int m = (blockIdx.x << 3) + (threadIdx.x >> 5);
    int lane = threadIdx.x & 31;
    const float* wr = W + (size_t)b * sW + (size_t)m * CCH;
    const float* vv = v + (size_t)b * sV;
    float s = 0.f;
    for (int k = lane; k < CCH; k += 32) s += wr[k] * vv[k];
#pragma unroll
    for (int o = 16; o > 0; o >>= 1) s += __shfl_xor_sync(0xffffffffu, s, o);
    if (lane == 0) y[(size_t)b * sY + m] = s + (bias ? bias[m] : 0.f);
}

// combined u = Wq hs, w = Wk hs (blockIdx.z selects)
__global__ void matvec_uw_kernel(const float* __restrict__ Wq, const float* __restrict__ Wk,
                                 const float* __restrict__ hs,
                                 float* __restrict__ u, float* __restrict__ w)
{
    const float* W = blockIdx.z ? Wk : Wq;
    float* y = blockIdx.z ? w : u;
    int b = blockIdx.y;
    int m = (blockIdx.x << 3) + (threadIdx.x >> 5);
    int lane = threadIdx.x & 31;
    const float* wr = W + (size_t)m * CCH;
    const float* vv = hs + (size_t)b * CCH;
    float s = 0.f;
    for (int k = lane; k < CCH; k += 32) s += wr[k] * vv[k];
#pragma unroll
    for (int o = 16; o > 0; o >>= 1) s += __shfl_xor_sync(0xffffffffu, s, o);
    if (lane == 0) y[(size_t)b * CCH + m] = s;
}

// ---------------- launch ----------------
extern "C" void kernel_launch(void* const* d_in, const int* in_sizes, int n_in,
                              void* d_out, int out_size)
{
    const float* x     = (const float*)d_in[0];
    const float* gamma = (const float*)d_in[1];
    const float* beta  = (const float*)d_in[2];
    const float* Wq    = (const float*)d_in[3];
    const float* bq    = (const float*)d_in[4];
    const float* Wk    = (const float*)d_in[5];
    const float* bk    = (const float*)d_in[6];
    const float* Wv    = (const float*)d_in[7];
    const float* bv    = (const float*)d_in[8];
    const float* Wo    = (const float*)d_in[9];
    const float* bo    = (const float*)d_in[10];
    float* out = (float*)d_out;

    float *hn, *hnT, *G, *T1, *S, *attn, *attnT, *T2, *P, *WvT, *hs, *u, *w, *t, *r;
    cudaGetSymbolAddress((void**)&hn,    g_hn);
    cudaGetSymbolAddress((void**)&hnT,   g_hnT);
    cudaGetSymbolAddress((void**)&G,     g_G);
    cudaGetSymbolAddress((void**)&T1,    g_T1);
    cudaGetSymbolAddress((void**)&S,     g_S);
    cudaGetSymbolAddress((void**)&attn,  g_attn);
    cudaGetSymbolAddress((void**)&attnT, g_attnT);
    cudaGetSymbolAddress((void**)&T2,    g_T2);
    cudaGetSymbolAddress((void**)&P,     g_P);
    cudaGetSymbolAddress((void**)&WvT,   g_WvT);
    cudaGetSymbolAddress((void**)&hs,    g_hs);
    cudaGetSymbolAddress((void**)&u,     g_u);
    cudaGetSymbolAddress((void**)&w,     g_w);
    cudaGetSymbolAddress((void**)&t,     g_t);
    cudaGetSymbolAddress((void**)&r,     g_r);

    cudaFuncSetAttribute(gemm_tc<false>, cudaFuncAttributeMaxDynamicSharedMemorySize, SMEM_PLAIN);
    cudaFuncSetAttribute(gemm_tc<true>,  cudaFuncAttributeMaxDynamicSharedMemorySize, SMEM_SPLIT);

    const long long sF  = (long long)CCH * NPIX;
    const long long sAt = (long long)CCH * CCH;
    const float scale = 1.0f / sqrtf((float)CCH);

    // 1) GroupNorm stats (+hs) + apply/transpose; bias-correction vectors; WvT
    gn_stats_kernel<<<BATCH * 32, 256>>>(x, gamma, beta, hs);
    gn_tr_kernel<<<dim3(NPIX / 32, CCH / 32, BATCH), 256>>>(x, gamma, beta, hn, hnT);
    matvec_uw_kernel<<<dim3(CCH / 8, BATCH, 2), 256>>>(Wq, Wk, hs, u, w);
    transpose_kernel<<<dim3(16, 16, 1), 256>>>(Wv, WvT, 0, 0);

    // 2) G = hn hn^T  (symmetric: 6 of 8 tiles, then mirror)   K=4096 heavy
    gemm_tc<false><<<dim3(6, 1, BATCH), 256, SMEM_PLAIN>>>(
        hn, NPIX, sF, hn, NPIX, sF, G, CCH, sAt, nullptr, 0, 0, nullptr, 1.f, NPIX, 1);
    mirror_kernel<<<dim3(8, 8, BATCH), 256>>>(G);

    // 3) T1 = Wq G (G symmetric); S = T1 Wk^T   (split-tf32 smalls)
    gemm_tc<true><<<dim3(4, 2, BATCH), 256, SMEM_SPLIT>>>(
        Wq, CCH, 0, G, CCH, sAt, T1, CCH, sAt, nullptr, 0, 0, nullptr, 1.f, CCH, 0);
    gemm_tc<true><<<dim3(4, 2, BATCH), 256, SMEM_SPLIT>>>(
        T1, CCH, sAt, Wk, CCH, 0, S, CCH, sAt, nullptr, 0, 0, nullptr, 1.f, CCH, 0);

    // 4) softmax (with exact rank-1 bias corrections), then transpose
    softmax_kernel<<<(BATCH * CCH * 32) / 256, 256>>>(S, attn, u, w, bq, bk, scale);
    transpose_kernel<<<dim3(16, 16, BATCH), 256>>>(attn, attnT, sAt, sAt);

    // 5) T2 = Wo attn (B=attnT); P = T2 Wv (B=WvT)   (split-tf32 smalls)
    gemm_tc<true><<<dim3(4, 2, BATCH), 256, SMEM_SPLIT>>>(
        Wo, CCH, 0, attnT, CCH, sAt, T2, CCH, sAt, nullptr, 0, 0, nullptr, 1.f, CCH, 0);
    gemm_tc<true><<<dim3(4, 2, BATCH), 256, SMEM_SPLIT>>>(
        T2, CCH, sAt, WvT, CCH, 0, P, CCH, sAt, nullptr, 0, 0, nullptr, 1.f, CCH, 0);

    // 6) r = Wo (attn bv) + bo
    matvec_kernel<<<dim3(CCH / 8, BATCH), 256>>>(attn, sAt, bv, 0, t, CCH, nullptr);
    matvec_kernel<<<dim3(CCH / 8, BATCH), 256>>>(Wo, 0, t, CCH, r, CCH, bo);

    // 7) out = P hn + r + x   K=512 heavy
    gemm_tc<false><<<dim3(NPIX / 128, 2, BATCH), 256, SMEM_PLAIN>>>(
        P, CCH, sAt, hnT, CCH, sF, out, NPIX, sF, r, 1, CCH, x, 1.f, CCH, 0);
}

// round 6
// speedup vs baseline: 7.5106x; 1.1987x over previous
#include <cuda_runtime.h>
#include <math.h>
#include <stdint.h>

#define BATCH 16
#define CCH   512
#define NPIX  4096
#define KSPLIT 4

// ---------------- scratch (__device__ globals; no allocation allowed) ----------------
__device__ float g_hn  [(size_t)BATCH * CCH * NPIX];   // normalized, [b, c, pixel]
__device__ float g_hnT [(size_t)BATCH * NPIX * CCH];   // [b, pixel, c]
__device__ float g_Gp  [(size_t)KSPLIT * BATCH * CCH * CCH];   // split-K partials
__device__ float g_G   [(size_t)BATCH * CCH * CCH];
__device__ float g_T1  [(size_t)BATCH * CCH * CCH];
__device__ float g_S   [(size_t)BATCH * CCH * CCH];
__device__ float g_attn[(size_t)BATCH * CCH * CCH];
__device__ float g_attnT[(size_t)BATCH * CCH * CCH];
__device__ float g_T2  [(size_t)BATCH * CCH * CCH];
__device__ float g_P   [(size_t)BATCH * CCH * CCH];
__device__ float g_WvT [(size_t)CCH * CCH];
__device__ float g_hs  [BATCH * CCH];
__device__ float g_u   [BATCH * CCH];
__device__ float g_w   [BATCH * CCH];
__device__ float g_t   [BATCH * CCH];
__device__ float g_r   [BATCH * CCH];
__device__ float2 g_stats[BATCH * 32];                 // mean, rstd per (b, group)

__device__ __forceinline__ float tf32r(float x) {   // round-to-nearest tf32
    float y; asm("cvt.rna.tf32.f32 %0, %1;" : "=f"(y) : "f"(x)); return y;
}

__device__ __forceinline__ void mma_tf32_16x8x8(float* d, const uint32_t* a, const uint32_t* b) {
    asm volatile(
        "mma.sync.aligned.m16n8k8.row.col.f32.tf32.tf32.f32 "
        "{%0,%1,%2,%3}, {%4,%5,%6,%7}, {%8,%9}, {%0,%1,%2,%3};"
        : "+f"(d[0]), "+f"(d[1]), "+f"(d[2]), "+f"(d[3])
        : "r"(a[0]), "r"(a[1]), "r"(a[2]), "r"(a[3]), "r"(b[0]), "r"(b[1]));
}

// ---------------- GroupNorm stats + per-channel hs: one block per (batch, group) ----------------
__global__ void gn_stats_kernel(const float* __restrict__ x,
                                const float* __restrict__ gamma,
                                const float* __restrict__ beta,
                                float* __restrict__ hs)
{
    int bg = blockIdx.x;
    int b = bg >> 5, g = bg & 31;
    size_t base = (size_t)bg * (16 * NPIX);
    int wid = threadIdx.x >> 5, lane = threadIdx.x & 31;
    __shared__ float chs[16], chss[16];

#pragma unroll
    for (int c2 = 0; c2 < 2; c2++) {
        int cl = wid * 2 + c2;
        const float4* xp = (const float4*)(x + base + (size_t)cl * NPIX);
        float s = 0.f, ss = 0.f;
        for (int i = lane; i < NPIX / 4; i += 32) {
            float4 v = xp[i];
            s  += v.x + v.y + v.z + v.w;
            ss += v.x * v.x + v.y * v.y + v.z * v.z + v.w * v.w;
        }
#pragma unroll
        for (int o = 16; o > 0; o >>= 1) {
            s  += __shfl_xor_sync(0xffffffffu, s, o);
            ss += __shfl_xor_sync(0xffffffffu, ss, o);
        }
        if (lane == 0) { chs[cl] = s; chss[cl] = ss; }
    }
    __syncthreads();
    if (threadIdx.x == 0) {
        float s = 0.f, ss = 0.f;
#pragma unroll
        for (int i = 0; i < 16; i++) { s += chs[i]; ss += chss[i]; }
        float mean = s * (1.f / (16 * NPIX));
        float var  = ss * (1.f / (16 * NPIX)) - mean * mean;
        g_stats[bg] = make_float2(mean, rsqrtf(var + 1e-6f));
    }
    __syncthreads();
    if (threadIdx.x < 16) {
        int cl = threadIdx.x, ch = g * 16 + cl;
        float2 st = g_stats[bg];
        float ga = gamma[ch] * st.y;
        float be = beta[ch] - st.x * ga;
        hs[(b << 9) + ch] = ga * chs[cl] + (float)NPIX * be;
    }
}

// ---------------- GroupNorm apply: x[b,c,hw] -> hn (same layout) + hnT[b,hw,c] ----------------
__global__ void __launch_bounds__(256) gn_tr_kernel(
    const float* __restrict__ x, const float* __restrict__ gamma,
    const float* __restrict__ beta, float* __restrict__ hn, float* __restrict__ hnT)
{
    __shared__ float ts[32][33];
    int b = blockIdx.z, ch0 = blockIdx.y << 5, px0 = blockIdx.x << 5;
    int tid = threadIdx.x;
    int cl = tid >> 3, f4 = tid & 7;
    int ch = ch0 + cl;
    float2 st = g_stats[(b << 5) + (ch >> 4)];
    float ga = gamma[ch] * st.y;
    float be = beta[ch] - st.x * ga;
    size_t off = (size_t)b * CCH * NPIX + (size_t)ch * NPIX + px0 + (f4 << 2);
    float4 v = *(const float4*)(x + off);
    v.x = v.x * ga + be; v.y = v.y * ga + be;
    v.z = v.z * ga + be; v.w = v.w * ga + be;
    *(float4*)(hn + off) = v;
    ts[cl][(f4 << 2) + 0] = v.x;
    ts[cl][(f4 << 2) + 1] = v.y;
    ts[cl][(f4 << 2) + 2] = v.z;
    ts[cl][(f4 << 2) + 3] = v.w;
    __syncthreads();
    int pl = tid >> 3, c4 = tid & 7;
    float4 o;
    o.x = ts[(c4 << 2) + 0][pl];
    o.y = ts[(c4 << 2) + 1][pl];
    o.z = ts[(c4 << 2) + 2][pl];
    o.w = ts[(c4 << 2) + 3][pl];
    float* hp = hnT + (size_t)b * NPIX * CCH + (size_t)(px0 + pl) * CCH + ch0 + (c4 << 2);
    *(float4*)hp = o;
}

// ---------------- tf32 mma.sync GEMM: D[M,N] = scale*A[M,K]*B[N,K]^T (+bias)(+resid) ----------------
// CTA 256x128, BK=32, 8 warps (4x2), warp tile 64x64, m16n8k8.
// sym=1: symmetric 512x512 output, 6 tiles via blockIdx.x, split-K via blockIdx.y.
#define A_SUB 132
#define B_SUB 66
#define A_FLOATS (64 * A_SUB)            // 8448
#define B_FLOATS (64 * B_SUB)            // 4224
#define STAGE_F (A_FLOATS + B_FLOATS)    // 12672 floats
#define SMEM_PLAIN (2 * STAGE_F * 4)     // 101376 B
#define SMEM_SPLIT (4 * STAGE_F * 4)     // 202752 B

template<bool SPLIT>
__global__ void __launch_bounds__(256, 1) gemm_tc(
    const float* __restrict__ A, int lda, long long sA,
    const float* __restrict__ B, int ldb, long long sB,
    float* __restrict__ D, int ldd, long long sD,
    const float* __restrict__ bias, int bias_mode, long long sBias,
    const float* __restrict__ resid, float scale, int K, int sym, long long sKsp)
{
    extern __shared__ float smem[];
    const int BUFSZ = (SPLIT ? 2 : 1) * STAGE_F;

    int tid = threadIdx.x, wid = tid >> 5, lane = tid & 31;
    int z = blockIdx.z;
    int row0, col0;
    if (sym) {
        int t = blockIdx.x;
        row0 = (t < 2) ? 0 : 256;
        col0 = ((t < 2) ? t : (t - 2)) << 7;
    } else {
        row0 = blockIdx.y << 8;
        col0 = blockIdx.x << 7;
    }

    A += (size_t)z * sA + (size_t)row0 * lda;
    B += (size_t)z * sB + (size_t)col0 * ldb;
    D += (size_t)z * sD;
    if (sym) {   // split-K: blockIdx.y = k-chunk
        A += (size_t)blockIdx.y * K;
        B += (size_t)blockIdx.y * K;
        D += (size_t)blockIdx.y * sKsp;
    }
    if (resid) resid += (size_t)z * sD;

    const int r_  = tid >> 3;
    const int c0_ = (tid & 7) << 2;
    const int kt_ = c0_ >> 3;
    int offA[8], offB[4];
#pragma unroll
    for (int i = 0; i < 8; i++) {
        int r = r_ + (i << 5);
        int mt = r >> 4, rr = r & 15;
        int regA = (((c0_ & 7) >= 4) ? 2 : 0) + ((rr >> 3) & 1);
        offA[i] = (mt * 4 + kt_) * A_SUB + ((rr & 7) << 4) + regA;
    }
#pragma unroll
    for (int i = 0; i < 4; i++) {
        int r = r_ + (i << 5);
        int nt = r >> 3, nn = r & 7;
        int regB = ((c0_ & 7) >= 4) ? 1 : 0;
        offB[i] = A_FLOATS + (nt * 4 + kt_) * B_SUB + (nn << 3) + regB;
    }
    const float* aG = A + (size_t)r_ * lda + c0_;
    const float* bG = B + (size_t)r_ * ldb + c0_;
    const size_t aStep = (size_t)32 * lda;
    const size_t bStep = (size_t)32 * ldb;

    const int wm4 = (wid & 3) * 4;
    const int wn8 = (wid >> 2) * 8;

    float acc[4][8][4];
#pragma unroll
    for (int mt = 0; mt < 4; mt++)
#pragma unroll
        for (int nt = 0; nt < 8; nt++)
#pragma unroll
            for (int rgi = 0; rgi < 4; rgi++) acc[mt][nt][rgi] = 0.f;

    const int NK = K >> 5;
    float4 ra[8], rb[4];

    auto stage_load = [&](int s) {
        const float* aN = aG + (size_t)s * 32;
        const float* bN = bG + (size_t)s * 32;
#pragma unroll
        for (int i = 0; i < 8; i++) ra[i] = *(const float4*)(aN + i * aStep);
#pragma unroll
        for (int i = 0; i < 4; i++) rb[i] = *(const float4*)(bN + i * bStep);
    };
    auto stage_store = [&](float* base) {
        float h;
#pragma unroll
        for (int i = 0; i < 8; i++) {
            float* sa = base + offA[i];
            h = tf32r(ra[i].x); sa[0]  = h; if (SPLIT) (base + STAGE_F + offA[i])[0]  = tf32r(ra[i].x - h);
            h = tf32r(ra[i].y); sa[4]  = h; if (SPLIT) (base + STAGE_F + offA[i])[4]  = tf32r(ra[i].y - h);
            h = tf32r(ra[i].z); sa[8]  = h; if (SPLIT) (base + STAGE_F + offA[i])[8]  = tf32r(ra[i].z - h);
            h = tf32r(ra[i].w); sa[12] = h; if (SPLIT) (base + STAGE_F + offA[i])[12] = tf32r(ra[i].w - h);
        }
#pragma unroll
        for (int i = 0; i < 4; i++) {
            float* sb = base + offB[i];
            h = tf32r(rb[i].x); sb[0] = h; if (SPLIT) (base + STAGE_F + offB[i])[0] = tf32r(rb[i].x - h);
            h = tf32r(rb[i].y); sb[2] = h; if (SPLIT) (base + STAGE_F + offB[i])[2] = tf32r(rb[i].y - h);
            h = tf32r(rb[i].z); sb[4] = h; if (SPLIT) (base + STAGE_F + offB[i])[4] = tf32r(rb[i].z - h);
            h = tf32r(rb[i].w); sb[6] = h; if (SPLIT) (base + STAGE_F + offB[i])[6] = tf32r(rb[i].w - h);
        }
    };

    stage_load(0);
    stage_store(smem);
    __syncthreads();

    for (int s = 0; s < NK; s++) {
        if (s + 1 < NK) stage_load(s + 1);
        const float* cS = smem + (s & 1) * BUFSZ;
#pragma unroll
        for (int kt = 0; kt < 4; kt++) {
            uint4 af[4]; uint2 bf[8];
#pragma unroll
            for (int mt = 0; mt < 4; mt++)
                af[mt] = *(const uint4*)(cS + ((wm4 + mt) * 4 + kt) * A_SUB + (lane << 2));
#pragma unroll
            for (int nt = 0; nt < 8; nt++)
                bf[nt] = *(const uint2*)(cS + A_FLOATS + ((wn8 + nt) * 4 + kt) * B_SUB + (lane << 1));
#pragma unroll
            for (int mt = 0; mt < 4; mt++)
#pragma unroll
                for (int nt = 0; nt < 8; nt++)
                    mma_tf32_16x8x8(acc[mt][nt], &af[mt].x, &bf[nt].x);
            if (SPLIT) {
                uint4 al[4]; uint2 bl[8];
#pragma unroll
                for (int mt = 0; mt < 4; mt++)
                    al[mt] = *(const uint4*)(cS + STAGE_F + ((wm4 + mt) * 4 + kt) * A_SUB + (lane << 2));
#pragma unroll
                for (int nt = 0; nt < 8; nt++)
                    bl[nt] = *(const uint2*)(cS + STAGE_F + A_FLOATS + ((wn8 + nt) * 4 + kt) * B_SUB + (lane << 1));
#pragma unroll
                for (int mt = 0; mt < 4; mt++)
#pragma unroll
                    for (int nt = 0; nt < 8; nt++) {
                        mma_tf32_16x8x8(acc[mt][nt], &af[mt].x, &bl[nt].x);
                        mma_tf32_16x8x8(acc[mt][nt], &al[mt].x, &bf[nt].x);
                    }
            }
        }
        if (s + 1 < NK) {
            stage_store(smem + ((s + 1) & 1) * BUFSZ);
            __syncthreads();
        }
    }

    const int lane4 = lane >> 2, laneq = lane & 3;
    const int wrow = row0 + (wid & 3) * 64;
    const int wcol = col0 + (wid >> 2) * 64;
#pragma unroll
    for (int mt = 0; mt < 4; mt++) {
#pragma unroll
        for (int half = 0; half < 2; half++) {
            int r = wrow + mt * 16 + lane4 + half * 8;
            float rb_ = (bias_mode == 1) ? bias[(size_t)z * sBias + r] : 0.f;
            float* drow = D + (size_t)r * ldd + wcol;
            const float* rrow = resid ? (resid + (size_t)r * ldd + wcol) : nullptr;
#pragma unroll
            for (int nt = 0; nt < 8; nt++) {
                int c = nt * 8 + laneq * 2;
                float2 o;
                o.x = acc[mt][nt][half * 2 + 0] * scale + rb_;
                o.y = acc[mt][nt][half * 2 + 1] * scale + rb_;
                if (bias_mode == 2) {
                    o.x += bias[(size_t)z * sBias + wcol + c];
                    o.y += bias[(size_t)z * sBias + wcol + c + 1];
                }
                if (rrow) { o.x += rrow[c]; o.y += rrow[c + 1]; }
                *(float2*)(drow + c) = o;
            }
        }
    }
}

// ---------------- reduce split-K partials of G (computed region only) ----------------
__global__ void __launch_bounds__(256) reduce_g_kernel(const float* __restrict__ Gp,
                                                       float* __restrict__ G)
{
    const size_t per = (size_t)BATCH * CCH * CCH;
    int b = blockIdx.y;
    int idx = (blockIdx.x * 256 + threadIdx.x) << 2;
    int i = idx >> 9, j = idx & 511;
    if (i < 256 && j >= 256) return;   // mirror region filled later
    size_t off = (size_t)b * CCH * CCH + idx;
    float4 s0 = *(const float4*)(Gp + off);
    float4 s1 = *(const float4*)(Gp + per + off);
    float4 s2 = *(const float4*)(Gp + 2 * per + off);
    float4 s3 = *(const float4*)(Gp + 3 * per + off);
    float4 o;
    o.x = (s0.x + s1.x) + (s2.x + s3.x);
    o.y = (s0.y + s1.y) + (s2.y + s3.y);
    o.z = (s0.z + s1.z) + (s2.z + s3.z);
    o.w = (s0.w + s1.w) + (s2.w + s3.w);
    *(float4*)(G + off) = o;
}

// ---------------- mirror upper-right block of symmetric G ----------------
__global__ void __launch_bounds__(256) mirror_kernel(float* __restrict__ G)
{
    __shared__ float t[32][33];
    float* Gb = G + (size_t)blockIdx.z * CCH * CCH;
    int i0 = blockIdx.y << 5, j0 = 256 + (blockIdx.x << 5);
    int lx = threadIdx.x & 31, ly = threadIdx.x >> 5;
#pragma unroll
    for (int ii = 0; ii < 4; ii++)
        t[ly + ii * 8][lx] = Gb[(size_t)(j0 + ly + ii * 8) * CCH + i0 + lx];
    __syncthreads();
#pragma unroll
    for (int ii = 0; ii < 4; ii++)
        Gb[(size_t)(i0 + ly + ii * 8) * CCH + j0 + lx] = t[lx][ly + ii * 8];
}

// ---------------- softmax with rank-1 bias corrections ----------------
__global__ void softmax_kernel(const float* __restrict__ S, float* __restrict__ attn,
                               const float* __restrict__ u, const float* __restrict__ w,
                               const float* __restrict__ bq, const float* __restrict__ bk,
                               float scale)
{
    int gw = (blockIdx.x * blockDim.x + threadIdx.x) >> 5;
    int lane = threadIdx.x & 31;
    if (gw >= BATCH * CCH) return;
    int b = gw >> 9, c = gw & 511;
    const float* row = S + (size_t)gw * CCH;
    float* orow = attn + (size_t)gw * CCH;
    float uc = u[(b << 9) + c], bqc = bq[c];
    float v[16];
    float m = -3.4e38f;
#pragma unroll
    for (int i = 0; i < 16; i++) {
        int d = lane + (i << 5);
        float bkd = bk[d], wd = w[(b << 9) + d];
        v[i] = scale * (row[d] + uc * bkd + bqc * wd + (float)NPIX * bqc * bkd);
        m = fmaxf(m, v[i]);
    }
#pragma unroll
    for (int o = 16; o > 0; o >>= 1) m = fmaxf(m, __shfl_xor_sync(0xffffffffu, m, o));
    float s = 0.f;
#pragma unroll
    for (int i = 0; i < 16; i++) { v[i] = __expf(v[i] - m); s += v[i]; }
#pragma unroll
    for (int o = 16; o > 0; o >>= 1) s += __shfl_xor_sync(0xffffffffu, s, o);
    float inv = 1.f / s;
#pragma unroll
    for (int i = 0; i < 16; i++) orow[lane + (i << 5)] = v[i] * inv;
}

// ---------------- 512x512 transpose (per batch z) ----------------
__global__ void __launch_bounds__(256) transpose_kernel(
    const float* __restrict__ in, float* __restrict__ out, long long sIn, long long sOut)
{
    __shared__ float t[32][33];
    int z = blockIdx.z;
    in  += (size_t)z * sIn;
    out += (size_t)z * sOut;
    int x0 = blockIdx.x << 5, y0 = blockIdx.y << 5;
    int lx = threadIdx.x & 31, ly = threadIdx.x >> 5;
#pragma unroll
    for (int i = 0; i < 4; i++)
        t[ly + i * 8][lx] = in[(size_t)(y0 + ly + i * 8) * CCH + x0 + lx];
    __syncthreads();
#pragma unroll
    for (int i = 0; i < 4; i++)
        out[(size_t)(x0 + ly + i * 8) * CCH + y0 + lx] = t[lx][ly + i * 8];
}

// ---------------- batched matvec ----------------
__global__ void matvec_kernel(const float* __restrict__ W, long long sW,
                              const float* __restrict__ v, long long sV,
                              float* __restrict__ y, long long sY,
                              const float* __restrict__ bias)
{
    int b = blockIdx.y;
    int m = (blockIdx.x << 3) + (threadIdx.x >> 5);
    int lane = threadIdx.x & 31;
    const float* wr = W + (size_t)b * sW + (size_t)m * CCH;
    const float* vv = v + (size_t)b * sV;
    float s = 0.f;
    for (int k = lane; k < CCH; k += 32) s += wr[k] * vv[k];
#pragma unroll
    for (int o = 16; o > 0; o >>= 1) s += __shfl_xor_sync(0xffffffffu, s, o);
    if (lane == 0) y[(size_t)b * sY + m] = s + (bias ? bias[m] : 0.f);
}

__global__ void matvec_uw_kernel(const float* __restrict__ Wq, const float* __restrict__ Wk,
                                 const float* __restrict__ hs,
                                 float* __restrict__ u, float* __restrict__ w)
{
    const float* W = blockIdx.z ? Wk : Wq;
    float* y = blockIdx.z ? w : u;
    int b = blockIdx.y;
    int m = (blockIdx.x << 3) + (threadIdx.x >> 5);
    int lane = threadIdx.x & 31;
    const float* wr = W + (size_t)m * CCH;
    const float* vv = hs + (size_t)b * CCH;
    float s = 0.f;
    for (int k = lane; k < CCH; k += 32) s += wr[k] * vv[k];
#pragma unroll
    for (int o = 16; o > 0; o >>= 1) s += __shfl_xor_sync(0xffffffffu, s, o);
    if (lane == 0) y[(size_t)b * CCH + m] = s;
}

// ---------------- launch ----------------
extern "C" void kernel_launch(void* const* d_in, const int* in_sizes, int n_in,
                              void* d_out, int out_size)
{
    const float* x     = (const float*)d_in[0];
    const float* gamma = (const float*)d_in[1];
    const float* beta  = (const float*)d_in[2];
    const float* Wq    = (const float*)d_in[3];
    const float* bq    = (const float*)d_in[4];
    const float* Wk    = (const float*)d_in[5];
    const float* bk    = (const float*)d_in[6];
    const float* Wv    = (const float*)d_in[7];
    const float* bv    = (const float*)d_in[8];
    const float* Wo    = (const float*)d_in[9];
    const float* bo    = (const float*)d_in[10];
    float* out = (float*)d_out;

    float *hn, *hnT, *Gp, *G, *T1, *S, *attn, *attnT, *T2, *P, *WvT, *hs, *u, *w, *t, *r;
    cudaGetSymbolAddress((void**)&hn,    g_hn);
    cudaGetSymbolAddress((void**)&hnT,   g_hnT);
    cudaGetSymbolAddress((void**)&Gp,    g_Gp);
    cudaGetSymbolAddress((void**)&G,     g_G);
    cudaGetSymbolAddress((void**)&T1,    g_T1);
    cudaGetSymbolAddress((void**)&S,     g_S);
    cudaGetSymbolAddress((void**)&attn,  g_attn);
    cudaGetSymbolAddress((void**)&attnT, g_attnT);
    cudaGetSymbolAddress((void**)&T2,    g_T2);
    cudaGetSymbolAddress((void**)&P,     g_P);
    cudaGetSymbolAddress((void**)&WvT,   g_WvT);
    cudaGetSymbolAddress((void**)&hs,    g_hs);
    cudaGetSymbolAddress((void**)&u,     g_u);
    cudaGetSymbolAddress((void**)&w,     g_w);
    cudaGetSymbolAddress((void**)&t,     g_t);
    cudaGetSymbolAddress((void**)&r,     g_r);

    cudaFuncSetAttribute(gemm_tc<false>, cudaFuncAttributeMaxDynamicSharedMemorySize, SMEM_PLAIN);
    cudaFuncSetAttribute(gemm_tc<true>,  cudaFuncAttributeMaxDynamicSharedMemorySize, SMEM_SPLIT);

    const long long sF  = (long long)CCH * NPIX;
    const long long sAt = (long long)CCH * CCH;
    const long long sKsp = (long long)BATCH * CCH * CCH;
    const float scale = 1.0f / sqrtf((float)CCH);

    // 1) GroupNorm stats (+hs) + apply/transpose; bias vectors; WvT
    gn_stats_kernel<<<BATCH * 32, 256>>>(x, gamma, beta, hs);
    gn_tr_kernel<<<dim3(NPIX / 32, CCH / 32, BATCH), 256>>>(x, gamma, beta, hn, hnT);
    matvec_uw_kernel<<<dim3(CCH / 8, BATCH, 2), 256>>>(Wq, Wk, hs, u, w);
    transpose_kernel<<<dim3(16, 16, 1), 256>>>(Wv, WvT, 0, 0);

    // 2) G = hn hn^T  symmetric, split-K=4 -> partials -> reduce -> mirror
    gemm_tc<false><<<dim3(6, KSPLIT, BATCH), 256, SMEM_PLAIN>>>(
        hn, NPIX, sF, hn, NPIX, sF, Gp, CCH, sAt, nullptr, 0, 0, nullptr, 1.f, NPIX / KSPLIT, 1, sKsp);
    reduce_g_kernel<<<dim3(256, BATCH), 256>>>(Gp, G);
    mirror_kernel<<<dim3(8, 8, BATCH), 256>>>(G);

    // 3) T1 = Wq G; S = T1 Wk^T   (split-tf32: score path precision)
    gemm_tc<true><<<dim3(4, 2, BATCH), 256, SMEM_SPLIT>>>(
        Wq, CCH, 0, G, CCH, sAt, T1, CCH, sAt, nullptr, 0, 0, nullptr, 1.f, CCH, 0, 0);
    gemm_tc<true><<<dim3(4, 2, BATCH), 256, SMEM_SPLIT>>>(
        T1, CCH, sAt, Wk, CCH, 0, S, CCH, sAt, nullptr, 0, 0, nullptr, 1.f, CCH, 0, 0);

    // 4) softmax (rank-1 bias corrections), transpose
    softmax_kernel<<<(BATCH * CCH * 32) / 256, 256>>>(S, attn, u, w, bq, bk, scale);
    transpose_kernel<<<dim3(16, 16, BATCH), 256>>>(attn, attnT, sAt, sAt);

    // 5) T2 = Wo attn; P = T2 Wv   (plain tf32: output path diluted by residual)
    gemm_tc<false><<<dim3(4, 2, BATCH), 256, SMEM_PLAIN>>>(
        Wo, CCH, 0, attnT, CCH, sAt, T2, CCH, sAt, nullptr, 0, 0, nullptr, 1.f, CCH, 0, 0);
    gemm_tc<false><<<dim3(4, 2, BATCH), 256, SMEM_PLAIN>>>(
        T2, CCH, sAt, WvT, CCH, 0, P, CCH, sAt, nullptr, 0, 0, nullptr, 1.f, CCH, 0, 0);

    // 6) r = Wo (attn bv) + bo
    matvec_kernel<<<dim3(CCH / 8, BATCH), 256>>>(attn, sAt, bv, 0, t, CCH, nullptr);
    matvec_kernel<<<dim3(CCH / 8, BATCH), 256>>>(Wo, 0, t, CCH, r, CCH, bo);

    // 7) out = P hn + r + x   K=512 heavy
    gemm_tc<false><<<dim3(NPIX / 128, 2, BATCH), 256, SMEM_PLAIN>>>(
        P, CCH, sAt, hnT, CCH, sF, out, NPIX, sF, r, 1, CCH, x, 1.f, CCH, 0, 0);
}

// round 7
// speedup vs baseline: 8.5867x; 1.1433x over previous
#include <cuda_runtime.h>
#include <math.h>
#include <stdint.h>

#define BATCH 16
#define CCH   512
#define NPIX  4096
#define KSPLIT 4

// ---------------- scratch (__device__ globals; no allocation allowed) ----------------
__device__ float g_xT  [(size_t)BATCH * NPIX * CCH];   // [b, pixel, c] raw x transposed
__device__ float g_Gp  [(size_t)KSPLIT * BATCH * CCH * CCH];   // split-K partials
__device__ float g_G   [(size_t)BATCH * CCH * CCH];
__device__ float g_T1  [(size_t)BATCH * CCH * CCH];
__device__ float g_S   [(size_t)BATCH * CCH * CCH];
__device__ float g_attn[(size_t)BATCH * CCH * CCH];
__device__ float g_attnT[(size_t)BATCH * CCH * CCH];
__device__ float g_T2  [(size_t)BATCH * CCH * CCH];
__device__ float g_P   [(size_t)BATCH * CCH * CCH];
__device__ float g_WvT [(size_t)CCH * CCH];
__device__ float g_ga  [BATCH * CCH];   // gamma * rstd (per batch,channel)
__device__ float g_be  [BATCH * CCH];   // beta - mean*ga
__device__ float g_sx  [BATCH * CCH];   // raw channel sums of x
__device__ float g_hs  [BATCH * CCH];   // ga*sx + N*be  (= row sums of hn)
__device__ float g_u   [BATCH * CCH];
__device__ float g_w   [BATCH * CCH];
__device__ float g_v1  [BATCH * CCH];
__device__ float g_t   [BATCH * CCH];
__device__ float g_r   [BATCH * CCH];

__device__ __forceinline__ float tf32r(float x) {   // round-to-nearest tf32
    float y; asm("cvt.rna.tf32.f32 %0, %1;" : "=f"(y) : "f"(x)); return y;
}

__device__ __forceinline__ void mma_tf32_16x8x8(float* d, const uint32_t* a, const uint32_t* b) {
    asm volatile(
        "mma.sync.aligned.m16n8k8.row.col.f32.tf32.tf32.f32 "
        "{%0,%1,%2,%3}, {%4,%5,%6,%7}, {%8,%9}, {%0,%1,%2,%3};"
        : "+f"(d[0]), "+f"(d[1]), "+f"(d[2]), "+f"(d[3])
        : "r"(a[0]), "r"(a[1]), "r"(a[2]), "r"(a[3]), "r"(b[0]), "r"(b[1]));
}

// ---------------- GroupNorm stats: one block per (batch, group); emits ga/be/sx/hs ----------------
__global__ void gn_stats_kernel(const float* __restrict__ x,
                                const float* __restrict__ gamma,
                                const float* __restrict__ beta)
{
    int bg = blockIdx.x;
    int b = bg >> 5, g = bg & 31;
    size_t base = (size_t)bg * (16 * NPIX);
    int wid = threadIdx.x >> 5, lane = threadIdx.x & 31;
    __shared__ float chs[16], chss[16];
    __shared__ float2 st_sh;

#pragma unroll
    for (int c2 = 0; c2 < 2; c2++) {
        int cl = wid * 2 + c2;
        const float4* xp = (const float4*)(x + base + (size_t)cl * NPIX);
        float s = 0.f, ss = 0.f;
        for (int i = lane; i < NPIX / 4; i += 32) {
            float4 v = xp[i];
            s  += v.x + v.y + v.z + v.w;
            ss += v.x * v.x + v.y * v.y + v.z * v.z + v.w * v.w;
        }
#pragma unroll
        for (int o = 16; o > 0; o >>= 1) {
            s  += __shfl_xor_sync(0xffffffffu, s, o);
            ss += __shfl_xor_sync(0xffffffffu, ss, o);
        }
        if (lane == 0) { chs[cl] = s; chss[cl] = ss; }
    }
    __syncthreads();
    if (threadIdx.x == 0) {
        float s = 0.f, ss = 0.f;
#pragma unroll
        for (int i = 0; i < 16; i++) { s += chs[i]; ss += chss[i]; }
        float mean = s * (1.f / (16 * NPIX));
        float var  = ss * (1.f / (16 * NPIX)) - mean * mean;
        st_sh = make_float2(mean, rsqrtf(var + 1e-6f));
    }
    __syncthreads();
    if (threadIdx.x < 16) {
        int cl = threadIdx.x, ch = g * 16 + cl;
        float2 st = st_sh;
        float ga = gamma[ch] * st.y;
        float be = beta[ch] - st.x * ga;
        float sx = chs[cl];
        int idx = (b << 9) + ch;
        g_ga[idx] = ga;
        g_be[idx] = be;
        g_sx[idx] = sx;
        g_hs[idx] = ga * sx + (float)NPIX * be;
    }
}

// ---------------- pure feature transpose: x[b,c,p] -> xT[b,p,c] ----------------
__global__ void __launch_bounds__(256) transpose_feat_kernel(
    const float* __restrict__ x, float* __restrict__ xT)
{
    __shared__ float ts[32][33];
    int b = blockIdx.z, ch0 = blockIdx.y << 5, px0 = blockIdx.x << 5;
    int tid = threadIdx.x;
    int cl = tid >> 3, f4 = tid & 7;
    size_t off = (size_t)b * CCH * NPIX + (size_t)(ch0 + cl) * NPIX + px0 + (f4 << 2);
    float4 v = *(const float4*)(x + off);
    ts[cl][(f4 << 2) + 0] = v.x;
    ts[cl][(f4 << 2) + 1] = v.y;
    ts[cl][(f4 << 2) + 2] = v.z;
    ts[cl][(f4 << 2) + 3] = v.w;
    __syncthreads();
    int pl = tid >> 3, c4 = tid & 7;
    float4 o;
    o.x = ts[(c4 << 2) + 0][pl];
    o.y = ts[(c4 << 2) + 1][pl];
    o.z = ts[(c4 << 2) + 2][pl];
    o.w = ts[(c4 << 2) + 3][pl];
    float* hp = xT + (size_t)b * NPIX * CCH + (size_t)(px0 + pl) * CCH + ch0 + (c4 << 2);
    *(float4*)hp = o;
}

// ---------------- tf32 mma.sync GEMM: D = scale*A*B^T (+bias)(+resid)(*cscale) ----------------
// CTA 256x128, BK=32, 8 warps (4x2), warp tile 64x64, m16n8k8.
#define A_SUB 132
#define B_SUB 66
#define A_FLOATS (64 * A_SUB)
#define B_FLOATS (64 * B_SUB)
#define STAGE_F (A_FLOATS + B_FLOATS)
#define SMEM_PLAIN (2 * STAGE_F * 4)     // 101376 B

__global__ void __launch_bounds__(256, 1) gemm_tc(
    const float* __restrict__ A, int lda, long long sA,
    const float* __restrict__ B, int ldb, long long sB,
    float* __restrict__ D, int ldd, long long sD,
    const float* __restrict__ bias, int bias_mode, long long sBias,
    const float* __restrict__ resid,
    const float* __restrict__ cscale,   // per-(batch, col) multiplier, stride CCH; nullable
    float scale, int K, int sym, long long sKsp)
{
    extern __shared__ float smem[];

    int tid = threadIdx.x, wid = tid >> 5, lane = tid & 31;
    int z = blockIdx.z;
    int row0, col0;
    if (sym) {
        int t = blockIdx.x;
        row0 = (t < 2) ? 0 : 256;
        col0 = ((t < 2) ? t : (t - 2)) << 7;
    } else {
        row0 = blockIdx.y << 8;
        col0 = blockIdx.x << 7;
    }

    A += (size_t)z * sA + (size_t)row0 * lda;
    B += (size_t)z * sB + (size_t)col0 * ldb;
    D += (size_t)z * sD;
    if (sym) {
        A += (size_t)blockIdx.y * K;
        B += (size_t)blockIdx.y * K;
        D += (size_t)blockIdx.y * sKsp;
    }
    if (resid) resid += (size_t)z * sD;

    const int r_  = tid >> 3;
    const int c0_ = (tid & 7) << 2;
    const int kt_ = c0_ >> 3;
    int offA[8], offB[4];
#pragma unroll
    for (int i = 0; i < 8; i++) {
        int r = r_ + (i << 5);
        int mt = r >> 4, rr = r & 15;
        int regA = (((c0_ & 7) >= 4) ? 2 : 0) + ((rr >> 3) & 1);
        offA[i] = (mt * 4 + kt_) * A_SUB + ((rr & 7) << 4) + regA;
    }
#pragma unroll
    for (int i = 0; i < 4; i++) {
        int r = r_ + (i << 5);
        int nt = r >> 3, nn = r & 7;
        int regB = ((c0_ & 7) >= 4) ? 1 : 0;
        offB[i] = A_FLOATS + (nt * 4 + kt_) * B_SUB + (nn << 3) + regB;
    }
    const float* aG = A + (size_t)r_ * lda + c0_;
    const float* bG = B + (size_t)r_ * ldb + c0_;
    const size_t aStep = (size_t)32 * lda;
    const size_t bStep = (size_t)32 * ldb;

    const int wm4 = (wid & 3) * 4;
    const int wn8 = (wid >> 2) * 8;

    float acc[4][8][4];
#pragma unroll
    for (int mt = 0; mt < 4; mt++)
#pragma unroll
        for (int nt = 0; nt < 8; nt++)
#pragma unroll
            for (int rgi = 0; rgi < 4; rgi++) acc[mt][nt][rgi] = 0.f;

    const int NK = K >> 5;
    float4 ra[8], rb[4];

    auto stage_load = [&](int s) {
        const float* aN = aG + (size_t)s * 32;
        const float* bN = bG + (size_t)s * 32;
#pragma unroll
        for (int i = 0; i < 8; i++) ra[i] = *(const float4*)(aN + i * aStep);
#pragma unroll
        for (int i = 0; i < 4; i++) rb[i] = *(const float4*)(bN + i * bStep);
    };
    auto stage_store = [&](float* base) {
#pragma unroll
        for (int i = 0; i < 8; i++) {
            float* sa = base + offA[i];
            sa[0]  = tf32r(ra[i].x);
            sa[4]  = tf32r(ra[i].y);
            sa[8]  = tf32r(ra[i].z);
            sa[12] = tf32r(ra[i].w);
        }
#pragma unroll
        for (int i = 0; i < 4; i++) {
            float* sb = base + offB[i];
            sb[0] = tf32r(rb[i].x);
            sb[2] = tf32r(rb[i].y);
            sb[4] = tf32r(rb[i].z);
            sb[6] = tf32r(rb[i].w);
        }
    };

    stage_load(0);
    stage_store(smem);
    __syncthreads();

    for (int s = 0; s < NK; s++) {
        if (s + 1 < NK) stage_load(s + 1);
        const float* cS = smem + (s & 1) * STAGE_F;
#pragma unroll
        for (int kt = 0; kt < 4; kt++) {
            uint4 af[4]; uint2 bf[8];
#pragma unroll
            for (int mt = 0; mt < 4; mt++)
                af[mt] = *(const uint4*)(cS + ((wm4 + mt) * 4 + kt) * A_SUB + (lane << 2));
#pragma unroll
            for (int nt = 0; nt < 8; nt++)
                bf[nt] = *(const uint2*)(cS + A_FLOATS + ((wn8 + nt) * 4 + kt) * B_SUB + (lane << 1));
#pragma unroll
            for (int mt = 0; mt < 4; mt++)
#pragma unroll
                for (int nt = 0; nt < 8; nt++)
                    mma_tf32_16x8x8(acc[mt][nt], &af[mt].x, &bf[nt].x);
        }
        if (s + 1 < NK) {
            stage_store(smem + ((s + 1) & 1) * STAGE_F);
            __syncthreads();
        }
    }

    const int lane4 = lane >> 2, laneq = lane & 3;
    const int wrow = row0 + (wid & 3) * 64;
    const int wcol = col0 + (wid >> 2) * 64;
#pragma unroll
    for (int mt = 0; mt < 4; mt++) {
#pragma unroll
        for (int half = 0; half < 2; half++) {
            int r = wrow + mt * 16 + lane4 + half * 8;
            float rb_ = (bias_mode == 1) ? bias[(size_t)z * sBias + r] : 0.f;
            float* drow = D + (size_t)r * ldd + wcol;
            const float* rrow = resid ? (resid + (size_t)r * ldd + wcol) : nullptr;
#pragma unroll
            for (int nt = 0; nt < 8; nt++) {
                int c = nt * 8 + laneq * 2;
                float2 o;
                o.x = acc[mt][nt][half * 2 + 0] * scale;
                o.y = acc[mt][nt][half * 2 + 1] * scale;
                if (cscale) {
                    o.x *= cscale[(size_t)z * CCH + wcol + c];
                    o.y *= cscale[(size_t)z * CCH + wcol + c + 1];
                }
                o.x += rb_; o.y += rb_;
                if (bias_mode == 2) {
                    o.x += bias[(size_t)z * sBias + wcol + c];
                    o.y += bias[(size_t)z * sBias + wcol + c + 1];
                }
                if (rrow) { o.x += rrow[c]; o.y += rrow[c + 1]; }
                *(float2*)(drow + c) = o;
            }
        }
    }
}

// ---------------- reduce split-K Gram partials + exact GN rank-1 corrections ----------------
// G[c,d] = ga_c ga_d Gx[c,d] + (ga_c sx_c) be_d + be_c hs_d
__global__ void __launch_bounds__(256) reduce_g_kernel(const float* __restrict__ Gp,
                                                       float* __restrict__ G)
{
    const size_t per = (size_t)BATCH * CCH * CCH;
    int b = blockIdx.y;
    int idx = (blockIdx.x * 256 + threadIdx.x) << 2;
    int i = idx >> 9, j = idx & 511;
    if (i < 256 && j >= 256) return;   // mirror region filled later
    size_t off = (size_t)b * CCH * CCH + idx;
    float4 s0 = *(const float4*)(Gp + off);
    float4 s1 = *(const float4*)(Gp + per + off);
    float4 s2 = *(const float4*)(Gp + 2 * per + off);
    float4 s3 = *(const float4*)(Gp + 3 * per + off);
    int ri = (b << 9) + i, rj = (b << 9) + j;
    float gai = g_ga[ri], hsxi = gai * g_sx[ri], bei = g_be[ri];
    float4 gaj = *(const float4*)(g_ga + rj);
    float4 bej = *(const float4*)(g_be + rj);
    float4 hsj = *(const float4*)(g_hs + rj);
    float4 o;
    o.x = gai * gaj.x * ((s0.x + s1.x) + (s2.x + s3.x)) + hsxi * bej.x + bei * hsj.x;
    o.y = gai * gaj.y * ((s0.y + s1.y) + (s2.y + s3.y)) + hsxi * bej.y + bei * hsj.y;
    o.z = gai * gaj.z * ((s0.z + s1.z) + (s2.z + s3.z)) + hsxi * bej.z + bei * hsj.z;
    o.w = gai * gaj.w * ((s0.w + s1.w) + (s2.w + s3.w)) + hsxi * bej.w + bei * hsj.w;
    *(float4*)(G + off) = o;
}

// ---------------- mirror upper-right block of symmetric G ----------------
__global__ void __launch_bounds__(256) mirror_kernel(float* __restrict__ G)
{
    __shared__ float t[32][33];
    float* Gb = G + (size_t)blockIdx.z * CCH * CCH;
    int i0 = blockIdx.y << 5, j0 = 256 + (blockIdx.x << 5);
    int lx = threadIdx.x & 31, ly = threadIdx.x >> 5;
#pragma unroll
    for (int ii = 0; ii < 4; ii++)
        t[ly + ii * 8][lx] = Gb[(size_t)(j0 + ly + ii * 8) * CCH + i0 + lx];
    __syncthreads();
#pragma unroll
    for (int ii = 0; ii < 4; ii++)
        Gb[(size_t)(i0 + ly + ii * 8) * CCH + j0 + lx] = t[lx][ly + ii * 8];
}

// ---------------- softmax with rank-1 bias corrections ----------------
__global__ void softmax_kernel(const float* __restrict__ S, float* __restrict__ attn,
                               const float* __restrict__ u, const float* __restrict__ w,
                               const float* __restrict__ bq, const float* __restrict__ bk,
                               float scale)
{
    int gw = (blockIdx.x * blockDim.x + threadIdx.x) >> 5;
    int lane = threadIdx.x & 31;
    if (gw >= BATCH * CCH) return;
    int b = gw >> 9, c = gw & 511;
    const float* row = S + (size_t)gw * CCH;
    float* orow = attn + (size_t)gw * CCH;
    float uc = u[(b << 9) + c], bqc = bq[c];
    float v[16];
    float m = -3.4e38f;
#pragma unroll
    for (int i = 0; i < 16; i++) {
        int d = lane + (i << 5);
        float bkd = bk[d], wd = w[(b << 9) + d];
        v[i] = scale * (row[d] + uc * bkd + bqc * wd + (float)NPIX * bqc * bkd);
        m = fmaxf(m, v[i]);
    }
#pragma unroll
    for (int o = 16; o > 0; o >>= 1) m = fmaxf(m, __shfl_xor_sync(0xffffffffu, m, o));
    float s = 0.f;
#pragma unroll
    for (int i = 0; i < 16; i++) { v[i] = __expf(v[i] - m); s += v[i]; }
#pragma unroll
    for (int o = 16; o > 0; o >>= 1) s += __shfl_xor_sync(0xffffffffu, s, o);
    float inv = 1.f / s;
#pragma unroll
    for (int i = 0; i < 16; i++) orow[lane + (i << 5)] = v[i] * inv;
}

// ---------------- 512x512 transpose (per batch z) ----------------
__global__ void __launch_bounds__(256) transpose_kernel(
    const float* __restrict__ in, float* __restrict__ out, long long sIn, long long sOut)
{
    __shared__ float t[32][33];
    int z = blockIdx.z;
    in  += (size_t)z * sIn;
    out += (size_t)z * sOut;
    int x0 = blockIdx.x << 5, y0 = blockIdx.y << 5;
    int lx = threadIdx.x & 31, ly = threadIdx.x >> 5;
#pragma unroll
    for (int i = 0; i < 4; i++)
        t[ly + i * 8][lx] = in[(size_t)(y0 + ly + i * 8) * CCH + x0 + lx];
    __syncthreads();
#pragma unroll
    for (int i = 0; i < 4; i++)
        out[(size_t)(x0 + ly + i * 8) * CCH + y0 + lx] = t[lx][ly + i * 8];
}

// ---------------- batched matvec: y[b,m] = W_b[m,:] . (v_b + v2) (+bias[m]) ----------------
__global__ void matvec_kernel(const float* __restrict__ W, long long sW,
                              const float* __restrict__ v, long long sV,
                              const float* __restrict__ v2,
                              float* __restrict__ y, long long sY,
                              const float* __restrict__ bias)
{
    int b = blockIdx.y;
    int m = (blockIdx.x << 3) + (threadIdx.x >> 5);
    int lane = threadIdx.x & 31;
    const float* wr = W + (size_t)b * sW + (size_t)m * CCH;
    const float* vv = v + (size_t)b * sV;
    float s = 0.f;
    for (int k = lane; k < CCH; k += 32) {
        float vk = vv[k];
        if (v2) vk += v2[k];
        s += wr[k] * vk;
    }
#pragma unroll
    for (int o = 16; o > 0; o >>= 1) s += __shfl_xor_sync(0xffffffffu, s, o);
    if (lane == 0) y[(size_t)b * sY + m] = s + (bias ? bias[m] : 0.f);
}

__global__ void matvec_uw_kernel(const float* __restrict__ Wq, const float* __restrict__ Wk,
                                 const float* __restrict__ hs,
                                 float* __restrict__ u, float* __restrict__ w)
{
    const float* W = blockIdx.z ? Wk : Wq;
    float* y = blockIdx.z ? w : u;
    int b = blockIdx.y;
    int m = (blockIdx.x << 3) + (threadIdx.x >> 5);
    int lane = threadIdx.x & 31;
    const float* wr = W + (size_t)m * CCH;
    const float* vv = hs + (size_t)b * CCH;
    float s = 0.f;
    for (int k = lane; k < CCH; k += 32) s += wr[k] * vv[k];
#pragma unroll
    for (int o = 16; o > 0; o >>= 1) s += __shfl_xor_sync(0xffffffffu, s, o);
    if (lane == 0) y[(size_t)b * CCH + m] = s;
}

// ---------------- launch ----------------
extern "C" void kernel_launch(void* const* d_in, const int* in_sizes, int n_in,
                              void* d_out, int out_size)
{
    const float* x     = (const float*)d_in[0];
    const float* gamma = (const float*)d_in[1];
    const float* beta  = (const float*)d_in[2];
    const float* Wq    = (const float*)d_in[3];
    const float* bq    = (const float*)d_in[4];
    const float* Wk    = (const float*)d_in[5];
    const float* bk    = (const float*)d_in[6];
    const float* Wv    = (const float*)d_in[7];
    const float* bv    = (const float*)d_in[8];
    const float* Wo    = (const float*)d_in[9];
    const float* bo    = (const float*)d_in[10];
    float* out = (float*)d_out;

    float *xT, *Gp, *G, *T1, *S, *attn, *attnT, *T2, *P, *WvT;
    float *ga, *be, *hs, *u, *w, *v1, *t, *r;
    cudaGetSymbolAddress((void**)&xT,    g_xT);
    cudaGetSymbolAddress((void**)&Gp,    g_Gp);
    cudaGetSymbolAddress((void**)&G,     g_G);
    cudaGetSymbolAddress((void**)&T1,    g_T1);
    cudaGetSymbolAddress((void**)&S,     g_S);
    cudaGetSymbolAddress((void**)&attn,  g_attn);
    cudaGetSymbolAddress((void**)&attnT, g_attnT);
    cudaGetSymbolAddress((void**)&T2,    g_T2);
    cudaGetSymbolAddress((void**)&P,     g_P);
    cudaGetSymbolAddress((void**)&WvT,   g_WvT);
    cudaGetSymbolAddress((void**)&ga,    g_ga);
    cudaGetSymbolAddress((void**)&be,    g_be);
    cudaGetSymbolAddress((void**)&hs,    g_hs);
    cudaGetSymbolAddress((void**)&u,     g_u);
    cudaGetSymbolAddress((void**)&w,     g_w);
    cudaGetSymbolAddress((void**)&v1,    g_v1);
    cudaGetSymbolAddress((void**)&t,     g_t);
    cudaGetSymbolAddress((void**)&r,     g_r);

    cudaFuncSetAttribute(gemm_tc, cudaFuncAttributeMaxDynamicSharedMemorySize, SMEM_PLAIN);

    const long long sF  = (long long)CCH * NPIX;
    const long long sAt = (long long)CCH * CCH;
    const long long sKsp = (long long)BATCH * CCH * CCH;
    const float scale = 1.0f / sqrtf((float)CCH);

    // 1) stats (ga/be/sx/hs), raw transpose, bias vectors, WvT
    gn_stats_kernel<<<BATCH * 32, 256>>>(x, gamma, beta);
    transpose_feat_kernel<<<dim3(NPIX / 32, CCH / 32, BATCH), 256>>>(x, xT);
    matvec_uw_kernel<<<dim3(CCH / 8, BATCH, 2), 256>>>(Wq, Wk, hs, u, w);
    transpose_kernel<<<dim3(16, 16, 1), 256>>>(Wv, WvT, 0, 0);

    // 2) Gx = x x^T (raw Gram), split-K, then reduce+GN corrections, mirror
    gemm_tc<<<dim3(6, KSPLIT, BATCH), 256, SMEM_PLAIN>>>(
        x, NPIX, sF, x, NPIX, sF, Gp, CCH, sAt,
        nullptr, 0, 0, nullptr, nullptr, 1.f, NPIX / KSPLIT, 1, sKsp);
    reduce_g_kernel<<<dim3(256, BATCH), 256>>>(Gp, G);
    mirror_kernel<<<dim3(8, 8, BATCH), 256>>>(G);

    // 3) T1 = Wq G; S = T1 Wk^T
    gemm_tc<<<dim3(4, 2, BATCH), 256, SMEM_PLAIN>>>(
        Wq, CCH, 0, G, CCH, sAt, T1, CCH, sAt, nullptr, 0, 0, nullptr, nullptr, 1.f, CCH, 0, 0);
    gemm_tc<<<dim3(4, 2, BATCH), 256, SMEM_PLAIN>>>(
        T1, CCH, sAt, Wk, CCH, 0, S, CCH, sAt, nullptr, 0, 0, nullptr, nullptr, 1.f, CCH, 0, 0);

    // 4) softmax (rank-1 bias corrections), transpose
    softmax_kernel<<<(BATCH * CCH * 32) / 256, 256>>>(S, attn, u, w, bq, bk, scale);
    transpose_kernel<<<dim3(16, 16, BATCH), 256>>>(attn, attnT, sAt, sAt);

    // 5) T2 = Wo attn; P' = (T2 Wv) * diag(ga)   (column scale fused in epilogue)
    gemm_tc<<<dim3(4, 2, BATCH), 256, SMEM_PLAIN>>>(
        Wo, CCH, 0, attnT, CCH, sAt, T2, CCH, sAt, nullptr, 0, 0, nullptr, nullptr, 1.f, CCH, 0, 0);
    gemm_tc<<<dim3(4, 2, BATCH), 256, SMEM_PLAIN>>>(
        T2, CCH, sAt, WvT, CCH, 0, P, CCH, sAt, nullptr, 0, 0, nullptr, ga, 1.f, CCH, 0, 0);

    // 6) r = Wo (attn (Wv be + bv)) + bo
    matvec_kernel<<<dim3(CCH / 8, BATCH), 256>>>(Wv, 0, be, CCH, nullptr, v1, CCH, nullptr);
    matvec_kernel<<<dim3(CCH / 8, BATCH), 256>>>(attn, sAt, v1, CCH, bv, t, CCH, nullptr);
    matvec_kernel<<<dim3(CCH / 8, BATCH), 256>>>(Wo, 0, t, CCH, nullptr, r, CCH, bo);

    // 7) out = P' x + r + x   K=512 heavy (B = raw transposed x)
    gemm_tc<<<dim3(NPIX / 128, 2, BATCH), 256, SMEM_PLAIN>>>(
        P, CCH, sAt, xT, CCH, sF, out, NPIX, sF, r, 1, CCH, x, nullptr, 1.f, CCH, 0, 0);
}